// round 6
// baseline (speedup 1.0000x reference)
#include <cuda_runtime.h>
#include <cuda_bf16.h>
#include <math.h>
#include <stdint.h>

// ---------------------------------------------------------------------------
// Problem constants
// ---------------------------------------------------------------------------
#define BATCH   16
#define CIN     3
#define IMG     256
#define PSZ     16
#define NPATCH  256
#define C5      15
#define PD      3840
#define DMODEL  768
#define DEPTH   8
#define MLP     3072
#define NCLS    1000
#define TTOK    257
#define NT      (BATCH*TTOK)        // 4112
#define NROWS_EMBED (BATCH*NPATCH)  // 4096
#define NHEAD   384

// weight plane offsets (elements)
#define WOFF_SPT  0
#define WSZ_SPT   (PD*DMODEL)
#define WOFF_INP  (WOFF_SPT + WSZ_SPT)
#define WSZ_INP   (DEPTH*DMODEL*3*DMODEL)
#define WOFF_OUTP (WOFF_INP + WSZ_INP)
#define WSZ_OUTP  (DEPTH*DMODEL*DMODEL)
#define WOFF_FF1  (WOFF_OUTP + WSZ_OUTP)
#define WSZ_FF1   (DEPTH*DMODEL*MLP)
#define WOFF_FF2  (WOFF_FF1 + WSZ_FF1)
#define WSZ_FF2   (DEPTH*MLP*DMODEL)
#define WTOT      (WOFF_FF2 + WSZ_FF2)

// ---------------------------------------------------------------------------
// Scratch (device globals)
// ---------------------------------------------------------------------------
__device__ __nv_bfloat16 g_wh[WTOT];
__device__ __nv_bfloat16 g_wl[WTOT];
__device__ __nv_bfloat16 g_ph[NROWS_EMBED * PD];
__device__ __nv_bfloat16 g_pl[NROWS_EMBED * PD];
__device__ __nv_bfloat16 g_xnh[NT * DMODEL];
__device__ __nv_bfloat16 g_xnl[NT * DMODEL];
__device__ __nv_bfloat16 g_oh[NT * DMODEL];
__device__ __nv_bfloat16 g_ol[NT * DMODEL];
__device__ __nv_bfloat16 g_hmh[NT * MLP];
__device__ __nv_bfloat16 g_hml[NT * MLP];
__device__ float g_x[NT * DMODEL];
__device__ float g_feat[NT * 3 * DMODEL];
__device__ float g_lb[DEPTH * DMODEL];
__device__ float g_cls[BATCH * DMODEL];

// ---------------------------------------------------------------------------
// Helpers
// ---------------------------------------------------------------------------
__device__ __forceinline__ uint32_t smem_u32(const void* p) {
    uint32_t a;
    asm("{ .reg .u64 t; cvta.to.shared.u64 t, %1; cvt.u32.u64 %0, t; }"
        : "=r"(a) : "l"(p));
    return a;
}
__device__ __forceinline__ void ldsm4(uint32_t* r, uint32_t addr) {
    asm volatile("ldmatrix.sync.aligned.m8n8.x4.shared.b16 {%0,%1,%2,%3}, [%4];"
                 : "=r"(r[0]), "=r"(r[1]), "=r"(r[2]), "=r"(r[3]) : "r"(addr));
}
__device__ __forceinline__ void ldsm4t(uint32_t* r, uint32_t addr) {
    asm volatile("ldmatrix.sync.aligned.m8n8.x4.trans.shared.b16 {%0,%1,%2,%3}, [%4];"
                 : "=r"(r[0]), "=r"(r[1]), "=r"(r[2]), "=r"(r[3]) : "r"(addr));
}
__device__ __forceinline__ void mma16816(float* d, const uint32_t* a, const uint32_t* b) {
    asm volatile(
        "mma.sync.aligned.m16n8k16.row.col.f32.bf16.bf16.f32 "
        "{%0,%1,%2,%3}, {%4,%5,%6,%7}, {%8,%9}, {%0,%1,%2,%3};"
        : "+f"(d[0]), "+f"(d[1]), "+f"(d[2]), "+f"(d[3])
        : "r"(a[0]), "r"(a[1]), "r"(a[2]), "r"(a[3]), "r"(b[0]), "r"(b[1]));
}
__device__ __forceinline__ void cpasync16(uint32_t dst, const void* src, uint32_t n) {
    asm volatile("cp.async.cg.shared.global [%0], [%1], 16, %2;"
                 :: "r"(dst), "l"(src), "r"(n) : "memory");
}
__device__ __forceinline__ void cp_commit() {
    asm volatile("cp.async.commit_group;" ::: "memory");
}
template<int N>
__device__ __forceinline__ void cp_wait() {
    asm volatile("cp.async.wait_group %0;" :: "n"(N) : "memory");
}

__device__ __forceinline__ float gelu_exact(float x) {
    return 0.5f * x * (1.f + erff(x * 0.70710678118654752440f));
}

__device__ __forceinline__ float blockReduceSum(float v) {
    __shared__ float sh[32];
    __shared__ float res;
    int lane = threadIdx.x & 31;
    int wid  = threadIdx.x >> 5;
    #pragma unroll
    for (int o = 16; o > 0; o >>= 1) v += __shfl_down_sync(0xffffffffu, v, o);
    if (lane == 0) sh[wid] = v;
    __syncthreads();
    int nw = (blockDim.x + 31) >> 5;
    v = (threadIdx.x < nw) ? sh[threadIdx.x] : 0.f;
    if (wid == 0) {
        #pragma unroll
        for (int o = 16; o > 0; o >>= 1) v += __shfl_down_sync(0xffffffffu, v, o);
        if (lane == 0) res = v;
    }
    __syncthreads();
    return res;
}

// fp32 -> (hi, lo) bf16
__device__ __forceinline__ void f2bf2(float v, uint32_t& h, uint32_t& l) {
    __nv_bfloat16 bh = __float2bfloat16_rn(v);
    float r = v - __bfloat162float(bh);
    __nv_bfloat16 bl = __float2bfloat16_rn(r);
    h = (uint32_t)__bfloat16_as_ushort(bh);
    l = (uint32_t)__bfloat16_as_ushort(bl);
}
__device__ __forceinline__ void cvt4(float4 v, uint2& h, uint2& l) {
    uint32_t h0,l0,h1,l1,h2,l2,h3,l3;
    f2bf2(v.x, h0, l0); f2bf2(v.y, h1, l1);
    f2bf2(v.z, h2, l2); f2bf2(v.w, h3, l3);
    h = make_uint2(h0 | (h1 << 16), h2 | (h3 << 16));
    l = make_uint2(l0 | (l1 << 16), l2 | (l3 << 16));
}

// ---------------------------------------------------------------------------
// Weight pre-conversion: all 5 weight tensors in ONE launch
// ---------------------------------------------------------------------------
__global__ __launch_bounds__(256)
void cvtw_all_k(const float* __restrict__ spt, const float* __restrict__ inp,
                const float* __restrict__ outp, const float* __restrict__ f1,
                const float* __restrict__ f2,
                __nv_bfloat16* __restrict__ h, __nv_bfloat16* __restrict__ l)
{
    size_t i = ((size_t)blockIdx.x * 256 + threadIdx.x) * 4;
    if (i >= WTOT) return;
    const float* src;
    size_t off;
    if (i < WOFF_INP)       { src = spt;  off = i - WOFF_SPT;  }
    else if (i < WOFF_OUTP) { src = inp;  off = i - WOFF_INP;  }
    else if (i < WOFF_FF1)  { src = outp; off = i - WOFF_OUTP; }
    else if (i < WOFF_FF2)  { src = f1;   off = i - WOFF_FF1;  }
    else                    { src = f2;   off = i - WOFF_FF2;  }
    float4 v = *reinterpret_cast<const float4*>(src + off);
    uint2 hh, ll;
    cvt4(v, hh, ll);
    *reinterpret_cast<uint2*>(h + i) = hh;
    *reinterpret_cast<uint2*>(l + i) = ll;
}

// ---------------------------------------------------------------------------
// x pre-init: x[b][t][:] = (t==0 ? cls_token : spt_b) + pos_emb[t]
// ---------------------------------------------------------------------------
__global__ __launch_bounds__(256)
void initx_k(const float* __restrict__ cls_token, const float* __restrict__ spt_b,
             const float* __restrict__ pos, float* __restrict__ x)
{
    int i = blockIdx.x * 256 + threadIdx.x;
    if (i >= NT * DMODEL) return;
    int row = i / DMODEL;
    int d   = i - row * DMODEL;
    int t   = row % TTOK;
    float base = (t == 0) ? cls_token[d] : spt_b[d];
    x[i] = base + pos[t * DMODEL + d];
}

// ---------------------------------------------------------------------------
// HMMA GEMM, bf16 hi/lo 3-pass, cp.async 2-stage pipeline.
// CTA tile 128x128, K-chunk 32, 4 warps (2m x 2n), warp tile 64x64.
// 2 CTAs/SM. Optional split-K via blockIdx.z (atomic epilogues).
// ---------------------------------------------------------------------------
#define EPI_STORE          0
#define EPI_GELU_PLANES    1
#define EPI_RESID_AT       2
#define EPI_BIAS_RESID_AT  3
#define EPI_EMBED_AT       4

#define NTHREADS 128
#define APITCH 80
#define BPITCH 272
#define OFF_AH 0
#define OFF_AL 10240
#define OFF_BH 20480
#define OFF_BL 29184
#define SBUF   37888
#define SMTOT  (2*SBUF)   // 75776, 2 CTAs/SM fit in 228KB

__device__ __forceinline__ void stage_load(uint32_t sb,
                                           const __nv_bfloat16* __restrict__ Ah,
                                           const __nv_bfloat16* __restrict__ Al,
                                           const __nv_bfloat16* __restrict__ Bh,
                                           const __nv_bfloat16* __restrict__ Bl,
                                           int M, int N, int lda,
                                           int rowBase, int colBase, int s, int tid)
{
    const int k0 = s << 5;
    // A: 128 rows x 64B per plane; 1 row per thread, 4 x 16B segs
    {
        int row = tid;
        int gr  = rowBase + row;
        uint32_t nbytes = (gr < M) ? 16u : 0u;
        int grs = (gr < M) ? gr : (M - 1);
        size_t gbase = (size_t)grs * lda + k0;
        uint32_t sbase = (uint32_t)(row * APITCH);
        #pragma unroll
        for (int seg = 0; seg < 4; seg++) {
            cpasync16(sb + OFF_AH + sbase + seg * 16, Ah + gbase + seg * 8, nbytes);
            cpasync16(sb + OFF_AL + sbase + seg * 16, Al + gbase + seg * 8, nbytes);
        }
    }
    // B: 32 rows x 256B per plane; 512 16B chunks / 128 threads = 4 each
    #pragma unroll
    for (int i = 0; i < 4; i++) {
        int idx = tid + i * 128;
        int row = idx >> 4;
        int seg = idx & 15;
        size_t goff = (size_t)(k0 + row) * N + colBase + seg * 8;
        uint32_t so = (uint32_t)(row * BPITCH + seg * 16);
        cpasync16(sb + OFF_BH + so, Bh + goff, 16u);
        cpasync16(sb + OFF_BL + so, Bl + goff, 16u);
    }
}

__device__ __forceinline__ void compute_chunk(uint32_t sbuf, int lane, int wm, int wn,
                                              float acc[4][8][4])
{
    #pragma unroll
    for (int k16 = 0; k16 < 32; k16 += 16) {
        uint32_t aH[4][4], aL[4][4], bH[4][4], bL[4][4];
        const uint32_t arow = (uint32_t)(wm + (lane & 7) + (lane & 8));
        const uint32_t aoff = arow * APITCH + (uint32_t)(k16 + ((lane & 16) >> 1)) * 2;
        #pragma unroll
        for (int mb = 0; mb < 4; mb++) {
            ldsm4(aH[mb], sbuf + OFF_AH + aoff + mb * 16 * APITCH);
            ldsm4(aL[mb], sbuf + OFF_AL + aoff + mb * 16 * APITCH);
        }
        const uint32_t brow = (uint32_t)(k16 + (lane & 7) + ((lane & 16) >> 1));
        const uint32_t boff = brow * BPITCH + (uint32_t)(wn + (lane & 8)) * 2;
        #pragma unroll
        for (int nb2 = 0; nb2 < 4; nb2++) {
            ldsm4t(bH[nb2], sbuf + OFF_BH + boff + nb2 * 32);
            ldsm4t(bL[nb2], sbuf + OFF_BL + boff + nb2 * 32);
        }
        #pragma unroll
        for (int mb = 0; mb < 4; mb++) {
            #pragma unroll
            for (int nb = 0; nb < 8; nb++) {
                uint32_t bh[2] = { bH[nb >> 1][nb & 1], bH[nb >> 1][(nb & 1) + 2] };
                uint32_t bl[2] = { bL[nb >> 1][nb & 1], bL[nb >> 1][(nb & 1) + 2] };
                mma16816(acc[mb][nb], aH[mb], bh);
                mma16816(acc[mb][nb], aH[mb], bl);
                mma16816(acc[mb][nb], aL[mb], bh);
            }
        }
    }
}

template<int EPI>
__global__ __launch_bounds__(NTHREADS, 2)
void mmagemm_k(const __nv_bfloat16* __restrict__ Ah, const __nv_bfloat16* __restrict__ Al,
               const __nv_bfloat16* __restrict__ Bh, const __nv_bfloat16* __restrict__ Bl,
               void* __restrict__ Cv, void* __restrict__ C2v,
               const float* __restrict__ bias,
               int M, int N, int lda, int Kslice)
{
    extern __shared__ char smem[];
    const uint32_t sbase = smem_u32(smem);
    const int tid  = threadIdx.x;
    const int lane = tid & 31;
    const int wid  = tid >> 5;
    const int wm   = (wid >> 1) * 64;
    const int wn   = (wid & 1) * 64;
    const int rowBase = blockIdx.y * 128;
    const int colBase = blockIdx.x * 128;
    const int kbeg = blockIdx.z * Kslice;
    const __nv_bfloat16* pAh = Ah + kbeg;
    const __nv_bfloat16* pAl = Al + kbeg;
    const __nv_bfloat16* pBh = Bh + (size_t)kbeg * N;
    const __nv_bfloat16* pBl = Bl + (size_t)kbeg * N;
    const int nc = Kslice >> 5;

    float acc[4][8][4];
    #pragma unroll
    for (int a = 0; a < 4; a++)
        #pragma unroll
        for (int b = 0; b < 8; b++)
            #pragma unroll
            for (int c = 0; c < 4; c++) acc[a][b][c] = 0.f;

    stage_load(sbase, pAh, pAl, pBh, pBl, M, N, lda, rowBase, colBase, 0, tid);
    cp_commit();

    for (int c = 0; c < nc; c++) {
        cp_wait<0>();
        __syncthreads();
        if (c + 1 < nc) {
            stage_load(sbase + ((c + 1) & 1) * SBUF, pAh, pAl, pBh, pBl, M, N, lda,
                       rowBase, colBase, c + 1, tid);
        }
        cp_commit();
        compute_chunk(sbase + (c & 1) * SBUF, lane, wm, wn, acc);
    }

    // ---- epilogue ----
    const int mrow = rowBase + wm + (lane >> 2);
    const int mcol = colBase + wn + ((lane & 3) << 1);
    #pragma unroll
    for (int mi = 0; mi < 4; mi++) {
        #pragma unroll
        for (int hf = 0; hf < 2; hf++) {
            const int row = mrow + mi * 16 + hf * 8;
            if (row >= M) continue;
            #pragma unroll
            for (int ni = 0; ni < 8; ni++) {
                const int col = mcol + ni * 8;
                float v0 = acc[mi][ni][hf * 2];
                float v1 = acc[mi][ni][hf * 2 + 1];
                if (EPI == EPI_STORE) {
                    float* C = (float*)Cv;
                    *reinterpret_cast<float2*>(C + (size_t)row * N + col) =
                        make_float2(v0, v1);
                } else if (EPI == EPI_GELU_PLANES) {
                    __nv_bfloat16* Hh = (__nv_bfloat16*)Cv;
                    __nv_bfloat16* Hl = (__nv_bfloat16*)C2v;
                    float2 bb = *reinterpret_cast<const float2*>(bias + col);
                    float g0 = gelu_exact(v0 + bb.x);
                    float g1 = gelu_exact(v1 + bb.y);
                    uint32_t h0,l0,h1,l1;
                    f2bf2(g0, h0, l0); f2bf2(g1, h1, l1);
                    size_t off = (size_t)row * N + col;
                    *reinterpret_cast<uint32_t*>(Hh + off) = h0 | (h1 << 16);
                    *reinterpret_cast<uint32_t*>(Hl + off) = l0 | (l1 << 16);
                } else if (EPI == EPI_RESID_AT) {
                    float* C = (float*)Cv;
                    size_t off = (size_t)row * N + col;
                    atomicAdd(C + off,     v0);
                    atomicAdd(C + off + 1, v1);
                } else if (EPI == EPI_BIAS_RESID_AT) {
                    float* C = (float*)Cv;
                    if (blockIdx.z == 0) {
                        float2 bb = *reinterpret_cast<const float2*>(bias + col);
                        v0 += bb.x;
                        v1 += bb.y;
                    }
                    size_t off = (size_t)row * N + col;
                    atomicAdd(C + off,     v0);
                    atomicAdd(C + off + 1, v1);
                } else if (EPI == EPI_EMBED_AT) {
                    float* C = (float*)Cv;
                    int b  = row >> 8;
                    int tl = row & 255;
                    size_t off = ((size_t)b * TTOK + 1 + tl) * N + col;
                    atomicAdd(C + off,     v0);
                    atomicAdd(C + off + 1, v1);
                }
            }
        }
    }
}

// ---------------------------------------------------------------------------
// Shifted-patch extraction + LayerNorm -> bf16 hi/lo planes
// ---------------------------------------------------------------------------
__global__ __launch_bounds__(256)
void patchln_k(const float* __restrict__ img,
               const float* __restrict__ ln_g,
               const float* __restrict__ ln_b,
               __nv_bfloat16* __restrict__ ph,
               __nv_bfloat16* __restrict__ pl)
{
    const int blk = blockIdx.x;
    const int b   = blk >> 8;
    const int pt  = blk & 255;
    const int phh = pt >> 4;
    const int pw  = pt & 15;

    __shared__ float vals[PD];

    const int sh_tab[5] = {0, 0, 0, 1, -1};
    const int sw_tab[5] = {0, 1, -1, 0, 0};

    float s = 0.f, ss = 0.f;
    for (int f = threadIdx.x; f < PD; f += 256) {
        int py  = f / (PSZ * C5);
        int rem = f - py * (PSZ * C5);
        int px  = rem / C5;
        int c   = rem - px * C5;
        int g   = c / CIN;
        int ch  = c - g * CIN;
        int row = phh * PSZ + py - sh_tab[g];
        int col = pw * PSZ + px - sw_tab[g];
        float v = 0.f;
        if (row >= 0 && row < IMG && col >= 0 && col < IMG)
            v = img[(((long)b * CIN + ch) * IMG + row) * IMG + col];
        vals[f] = v;
        s  += v;
        ss += v * v;
    }
    float tsum  = blockReduceSum(s);
    float tsum2 = blockReduceSum(ss);
    float mean  = tsum * (1.f / PD);
    float var   = tsum2 * (1.f / PD) - mean * mean;
    float rstd  = rsqrtf(var + 1e-5f);
    __syncthreads();
    size_t rowoff = (size_t)blk * PD;
    for (int f = threadIdx.x; f < PD; f += 256) {
        float y = (vals[f] - mean) * rstd * ln_g[f] + ln_b[f];
        uint32_t hh, ll;
        f2bf2(y, hh, ll);
        ph[rowoff + f] = __ushort_as_bfloat16((unsigned short)hh);
        pl[rowoff + f] = __ushort_as_bfloat16((unsigned short)ll);
    }
}

// ---------------------------------------------------------------------------
__global__ void lb_k(const float* __restrict__ lbin, float* __restrict__ lbout)
{
    int d = blockIdx.x * blockDim.x + threadIdx.x;
    if (d >= DMODEL) return;
    float v[DEPTH];
    float m = -1e30f;
    #pragma unroll
    for (int i = 0; i < DEPTH; i++) { v[i] = lbin[i * DMODEL + d]; m = fmaxf(m, v[i]); }
    float s = 0.f;
    #pragma unroll
    for (int i = 0; i < DEPTH; i++) { v[i] = expf(v[i] - m); s += v[i]; }
    float inv = 1.f / s;
    float c = 0.f;
    float c0 = v[0] * inv;
    #pragma unroll
    for (int i = 0; i < DEPTH; i++) { c += v[i] * inv; lbout[i * DMODEL + d] = c - c0; }
}

// RMSNorm -> bf16 hi/lo planes
__global__ __launch_bounds__(256)
void rmsnorm_k(const float* __restrict__ x,
               __nv_bfloat16* __restrict__ yh, __nv_bfloat16* __restrict__ yl)
{
    const long row = blockIdx.x;
    const float* xr = x + row * DMODEL;
    float s = 0.f;
    for (int i = threadIdx.x; i < DMODEL; i += 256) { float v = xr[i]; s += v * v; }
    float tot = blockReduceSum(s);
    float r = rsqrtf(tot * (1.f / DMODEL) + 1e-6f);
    size_t off = (size_t)row * DMODEL;
    for (int i = threadIdx.x; i < DMODEL; i += 256) {
        uint32_t hh, ll;
        f2bf2(xr[i] * r, hh, ll);
        yh[off + i] = __ushort_as_bfloat16((unsigned short)hh);
        yl[off + i] = __ushort_as_bfloat16((unsigned short)ll);
    }
}

// hGRU2 scan -> bf16 hi/lo planes
__global__ __launch_bounds__(256)
void hgru_k(const float* __restrict__ feat, const float* __restrict__ lb,
            __nv_bfloat16* __restrict__ oh, __nv_bfloat16* __restrict__ ol)
{
    int e = blockIdx.x * blockDim.x + threadIdx.x;
    if (e >= TTOK * NHEAD) return;
    int t = e / NHEAD;
    int h = e - t * NHEAD;

    float lb0 = lb[2 * h];
    float lb1 = lb[2 * h + 1];
    float S00 = 0.f, S01 = 0.f, S10 = 0.f, S11 = 0.f;

    #pragma unroll 1
    for (int n = 0; n < BATCH; n++) {
        const float* r = feat + (long)(n * TTOK + t) * (3 * DMODEL);
        float2 vv = *(const float2*)(r + 2 * h);
        float2 qq = *(const float2*)(r + DMODEL + 2 * h);
        float2 ff = *(const float2*)(r + 2 * DMODEL + 2 * h);
        float v0 = gelu_exact(vv.x), v1 = gelu_exact(vv.y);
        float q0 = gelu_exact(qq.x), q1 = gelu_exact(qq.y);
        float s0 = 1.f / (1.f + expf(-ff.x));
        float s1 = 1.f / (1.f + expf(-ff.y));
        float lam0 = lb0 + (1.f - lb0) * s0;
        float lam1 = lb1 + (1.f - lb1) * s1;
        float k0 = 1.f - lam0, k1 = 1.f - lam1;
        S00 = lam0 * S00 + k0 * v0;  S01 = lam0 * S01 + k0 * v1;
        S10 = lam1 * S10 + k1 * v0;  S11 = lam1 * S11 + k1 * v1;
        float o0 = q0 * S00 + q1 * S10;
        float o1 = q0 * S01 + q1 * S11;
        uint32_t h0,l0,h1,l1;
        f2bf2(o0, h0, l0); f2bf2(o1, h1, l1);
        size_t off = (size_t)(n * TTOK + t) * DMODEL + 2 * h;
        *reinterpret_cast<uint32_t*>(oh + off) = h0 | (h1 << 16);
        *reinterpret_cast<uint32_t*>(ol + off) = l0 | (l1 << 16);
    }
}

__global__ __launch_bounds__(256)
void final_k(const float* __restrict__ x,
             const float* __restrict__ g, const float* __restrict__ bvec,
             float* __restrict__ cls)
{
    int b = blockIdx.x;
    const float* xr = x + (long)b * TTOK * DMODEL;
    __shared__ float y[DMODEL];
    float s = 0.f, ss = 0.f;
    for (int i = threadIdx.x; i < DMODEL; i += 256) {
        float v = xr[i];
        y[i] = v;
        s  += v;
        ss += v * v;
    }
    float tsum  = blockReduceSum(s);
    float tsum2 = blockReduceSum(ss);
    float rstd1 = rsqrtf(tsum2 * (1.f / DMODEL) + 1e-6f);
    float mean  = rstd1 * tsum * (1.f / DMODEL);
    float ez2   = rstd1 * rstd1 * tsum2 * (1.f / DMODEL);
    float var   = ez2 - mean * mean;
    float rstd2 = rsqrtf(var + 1e-5f);
    __syncthreads();
    for (int i = threadIdx.x; i < DMODEL; i += 256) {
        float z = y[i] * rstd1;
        cls[(long)b * DMODEL + i] = (z - mean) * rstd2 * g[i] + bvec[i];
    }
}

__global__ __launch_bounds__(256)
void head_k(const float* __restrict__ cls, const float* __restrict__ w,
            const float* __restrict__ bias, float* __restrict__ out)
{
    int idx = blockIdx.x * blockDim.x + threadIdx.x;
    if (idx >= BATCH * NCLS) return;
    int b = idx / NCLS, c = idx - b * NCLS;
    const float* xr = cls + (long)b * DMODEL;
    float s = bias[c];
    #pragma unroll 4
    for (int k = 0; k < DMODEL; k++)
        s = fmaf(xr[k], w[(long)k * NCLS + c], s);
    out[idx] = s;
}

// ---------------------------------------------------------------------------
// Launch
// ---------------------------------------------------------------------------
extern "C" void kernel_launch(void* const* d_in, const int* in_sizes, int n_in,
                              void* d_out, int out_size)
{
    const float* img          = (const float*)d_in[0];
    const float* spt_ln_g     = (const float*)d_in[1];
    const float* spt_ln_b     = (const float*)d_in[2];
    const float* spt_w        = (const float*)d_in[3];
    const float* spt_b        = (const float*)d_in[4];
    const float* pos_emb      = (const float*)d_in[5];
    const float* cls_token    = (const float*)d_in[6];
    const float* lower_bounds = (const float*)d_in[7];
    const float* in_proj_w    = (const float*)d_in[8];
    const float* out_proj_w   = (const float*)d_in[9];
    const float* ff_w1        = (const float*)d_in[10];
    const float* ff_b1        = (const float*)d_in[11];
    const float* ff_w2        = (const float*)d_in[12];
    const float* ff_b2        = (const float*)d_in[13];
    const float* head_ln_g    = (const float*)d_in[14];
    const float* head_ln_b    = (const float*)d_in[15];
    const float* head_w       = (const float*)d_in[16];
    const float* head_b       = (const float*)d_in[17];

    __nv_bfloat16 *wh, *wl, *ph, *pl, *xnh, *xnl, *oh, *ol, *hmh, *hml;
    float *x, *feat, *lb, *cls;
    cudaGetSymbolAddress((void**)&wh,   g_wh);
    cudaGetSymbolAddress((void**)&wl,   g_wl);
    cudaGetSymbolAddress((void**)&ph,   g_ph);
    cudaGetSymbolAddress((void**)&pl,   g_pl);
    cudaGetSymbolAddress((void**)&xnh,  g_xnh);
    cudaGetSymbolAddress((void**)&xnl,  g_xnl);
    cudaGetSymbolAddress((void**)&oh,   g_oh);
    cudaGetSymbolAddress((void**)&ol,   g_ol);
    cudaGetSymbolAddress((void**)&hmh,  g_hmh);
    cudaGetSymbolAddress((void**)&hml,  g_hml);
    cudaGetSymbolAddress((void**)&x,    g_x);
    cudaGetSymbolAddress((void**)&feat, g_feat);
    cudaGetSymbolAddress((void**)&lb,   g_lb);
    cudaGetSymbolAddress((void**)&cls,  g_cls);

    static bool attr_done = false;
    if (!attr_done) {
        cudaFuncSetAttribute(mmagemm_k<EPI_STORE>,         cudaFuncAttributeMaxDynamicSharedMemorySize, SMTOT);
        cudaFuncSetAttribute(mmagemm_k<EPI_GELU_PLANES>,   cudaFuncAttributeMaxDynamicSharedMemorySize, SMTOT);
        cudaFuncSetAttribute(mmagemm_k<EPI_RESID_AT>,      cudaFuncAttributeMaxDynamicSharedMemorySize, SMTOT);
        cudaFuncSetAttribute(mmagemm_k<EPI_BIAS_RESID_AT>, cudaFuncAttributeMaxDynamicSharedMemorySize, SMTOT);
        cudaFuncSetAttribute(mmagemm_k<EPI_EMBED_AT>,      cudaFuncAttributeMaxDynamicSharedMemorySize, SMTOT);
        attr_done = true;
    }

    // (0) x pre-init (cls/bias/pos), (1) patch LN, (2) weight planes
    initx_k<<<(NT * DMODEL + 255) / 256, 256>>>(cls_token, spt_b, pos_emb, x);
    patchln_k<<<NROWS_EMBED, 256>>>(img, spt_ln_g, spt_ln_b, ph, pl);
    cvtw_all_k<<<(int)((WTOT / 4 + 255) / 256), 256>>>(spt_w, in_proj_w, out_proj_w,
                                                       ff_w1, ff_w2, wh, wl);
    // (3) embed GEMM, split-K4, atomic accumulate onto pre-initialized x
    {
        dim3 grid(DMODEL / 128, NROWS_EMBED / 128, 4);
        mmagemm_k<EPI_EMBED_AT><<<grid, NTHREADS, SMTOT>>>(
            ph, pl, wh + WOFF_SPT, wl + WOFF_SPT,
            x, nullptr, nullptr, NROWS_EMBED, DMODEL, PD, PD / 4);
    }
    lb_k<<<(DMODEL + 255) / 256, 256>>>(lower_bounds, lb);

    for (int i = 0; i < DEPTH; i++) {
        rmsnorm_k<<<NT, 256>>>(x, xnh, xnl);
        {
            dim3 grid((3 * DMODEL) / 128, (NT + 127) / 128, 1);
            mmagemm_k<EPI_STORE><<<grid, NTHREADS, SMTOT>>>(
                xnh, xnl,
                wh + WOFF_INP + (size_t)i * DMODEL * 3 * DMODEL,
                wl + WOFF_INP + (size_t)i * DMODEL * 3 * DMODEL,
                feat, nullptr, nullptr, NT, 3 * DMODEL, DMODEL, DMODEL);
        }
        hgru_k<<<(TTOK * NHEAD + 255) / 256, 256>>>(feat, lb + (size_t)i * DMODEL, oh, ol);
        {
            dim3 grid(DMODEL / 128, (NT + 127) / 128, 4);
            mmagemm_k<EPI_RESID_AT><<<grid, NTHREADS, SMTOT>>>(
                oh, ol,
                wh + WOFF_OUTP + (size_t)i * DMODEL * DMODEL,
                wl + WOFF_OUTP + (size_t)i * DMODEL * DMODEL,
                x, nullptr, nullptr, NT, DMODEL, DMODEL, DMODEL / 4);
        }
        rmsnorm_k<<<NT, 256>>>(x, xnh, xnl);
        {
            dim3 grid(MLP / 128, (NT + 127) / 128, 1);
            mmagemm_k<EPI_GELU_PLANES><<<grid, NTHREADS, SMTOT>>>(
                xnh, xnl,
                wh + WOFF_FF1 + (size_t)i * DMODEL * MLP,
                wl + WOFF_FF1 + (size_t)i * DMODEL * MLP,
                hmh, hml, ff_b1 + (size_t)i * MLP, NT, MLP, DMODEL, DMODEL);
        }
        {
            dim3 grid(DMODEL / 128, (NT + 127) / 128, 4);
            mmagemm_k<EPI_BIAS_RESID_AT><<<grid, NTHREADS, SMTOT>>>(
                hmh, hml,
                wh + WOFF_FF2 + (size_t)i * MLP * DMODEL,
                wl + WOFF_FF2 + (size_t)i * MLP * DMODEL,
                x, nullptr, ff_b2 + (size_t)i * DMODEL, NT, DMODEL, MLP, MLP / 4);
        }
    }

    final_k<<<BATCH, 256>>>(x, head_ln_g, head_ln_b, cls);
    head_k<<<(BATCH * NCLS + 255) / 256, 256>>>(cls, head_w, head_b, (float*)d_out);
}

// round 7
// speedup vs baseline: 1.1325x; 1.1325x over previous
#include <cuda_runtime.h>
#include <cuda_fp16.h>
#include <math.h>
#include <stdint.h>

// ---------------------------------------------------------------------------
// Problem constants
// ---------------------------------------------------------------------------
#define BATCH   16
#define CIN     3
#define IMG     256
#define PSZ     16
#define NPATCH  256
#define C5      15
#define PD      3840
#define DMODEL  768
#define DEPTH   8
#define MLP     3072
#define NCLS    1000
#define TTOK    257
#define NT      (BATCH*TTOK)        // 4112
#define NROWS_EMBED (BATCH*NPATCH)  // 4096
#define NHEAD   384

// weight plane offsets (elements)
#define WOFF_SPT  0
#define WSZ_SPT   (PD*DMODEL)
#define WOFF_INP  (WOFF_SPT + WSZ_SPT)
#define WSZ_INP   (DEPTH*DMODEL*3*DMODEL)
#define WOFF_OUTP (WOFF_INP + WSZ_INP)
#define WSZ_OUTP  (DEPTH*DMODEL*DMODEL)
#define WOFF_FF1  (WOFF_OUTP + WSZ_OUTP)
#define WSZ_FF1   (DEPTH*DMODEL*MLP)
#define WOFF_FF2  (WOFF_FF1 + WSZ_FF1)
#define WSZ_FF2   (DEPTH*MLP*DMODEL)
#define WTOT      (WOFF_FF2 + WSZ_FF2)

// ---------------------------------------------------------------------------
// Scratch (device globals)
// ---------------------------------------------------------------------------
__device__ __half g_wh[WTOT];                 // weights: single fp16 plane
__device__ __half g_ph[NROWS_EMBED * PD];     // activations: hi/lo fp16 planes
__device__ __half g_pl[NROWS_EMBED * PD];
__device__ __half g_xnh[NT * DMODEL];
__device__ __half g_xnl[NT * DMODEL];
__device__ __half g_oh[NT * DMODEL];
__device__ __half g_ol[NT * DMODEL];
__device__ __half g_hmh[NT * MLP];
__device__ __half g_hml[NT * MLP];
__device__ float g_x[NT * DMODEL];
__device__ float g_feat[NT * 3 * DMODEL];
__device__ float g_lb[DEPTH * DMODEL];
__device__ float g_cls[BATCH * DMODEL];

// ---------------------------------------------------------------------------
// Helpers
// ---------------------------------------------------------------------------
__device__ __forceinline__ uint32_t smem_u32(const void* p) {
    uint32_t a;
    asm("{ .reg .u64 t; cvta.to.shared.u64 t, %1; cvt.u32.u64 %0, t; }"
        : "=r"(a) : "l"(p));
    return a;
}
__device__ __forceinline__ void ldsm4(uint32_t* r, uint32_t addr) {
    asm volatile("ldmatrix.sync.aligned.m8n8.x4.shared.b16 {%0,%1,%2,%3}, [%4];"
                 : "=r"(r[0]), "=r"(r[1]), "=r"(r[2]), "=r"(r[3]) : "r"(addr));
}
__device__ __forceinline__ void ldsm4t(uint32_t* r, uint32_t addr) {
    asm volatile("ldmatrix.sync.aligned.m8n8.x4.trans.shared.b16 {%0,%1,%2,%3}, [%4];"
                 : "=r"(r[0]), "=r"(r[1]), "=r"(r[2]), "=r"(r[3]) : "r"(addr));
}
__device__ __forceinline__ void mma16816(float* d, const uint32_t* a, const uint32_t* b) {
    asm volatile(
        "mma.sync.aligned.m16n8k16.row.col.f32.f16.f16.f32 "
        "{%0,%1,%2,%3}, {%4,%5,%6,%7}, {%8,%9}, {%0,%1,%2,%3};"
        : "+f"(d[0]), "+f"(d[1]), "+f"(d[2]), "+f"(d[3])
        : "r"(a[0]), "r"(a[1]), "r"(a[2]), "r"(a[3]), "r"(b[0]), "r"(b[1]));
}
__device__ __forceinline__ void cpasync16(uint32_t dst, const void* src, uint32_t n) {
    asm volatile("cp.async.cg.shared.global [%0], [%1], 16, %2;"
                 :: "r"(dst), "l"(src), "r"(n) : "memory");
}
__device__ __forceinline__ void cp_commit() {
    asm volatile("cp.async.commit_group;" ::: "memory");
}
template<int N>
__device__ __forceinline__ void cp_wait() {
    asm volatile("cp.async.wait_group %0;" :: "n"(N) : "memory");
}

__device__ __forceinline__ float gelu_exact(float x) {
    return 0.5f * x * (1.f + erff(x * 0.70710678118654752440f));
}

__device__ __forceinline__ float blockReduceSum(float v) {
    __shared__ float sh[32];
    __shared__ float res;
    int lane = threadIdx.x & 31;
    int wid  = threadIdx.x >> 5;
    #pragma unroll
    for (int o = 16; o > 0; o >>= 1) v += __shfl_down_sync(0xffffffffu, v, o);
    if (lane == 0) sh[wid] = v;
    __syncthreads();
    int nw = (blockDim.x + 31) >> 5;
    v = (threadIdx.x < nw) ? sh[threadIdx.x] : 0.f;
    if (wid == 0) {
        #pragma unroll
        for (int o = 16; o > 0; o >>= 1) v += __shfl_down_sync(0xffffffffu, v, o);
        if (lane == 0) res = v;
    }
    __syncthreads();
    return res;
}

// fp32 -> (hi, lo) fp16
__device__ __forceinline__ void f2h2(float v, uint32_t& h, uint32_t& l) {
    __half hh = __float2half_rn(v);
    float r = v - __half2float(hh);
    __half ll = __float2half_rn(r);
    h = (uint32_t)__half_as_ushort(hh);
    l = (uint32_t)__half_as_ushort(ll);
}
// fp32x4 -> packed fp16 hi plane only
__device__ __forceinline__ uint2 cvt4h(float4 v) {
    __half2 a = __floats2half2_rn(v.x, v.y);
    __half2 b = __floats2half2_rn(v.z, v.w);
    return make_uint2(*reinterpret_cast<uint32_t*>(&a), *reinterpret_cast<uint32_t*>(&b));
}

// ---------------------------------------------------------------------------
// Weight pre-conversion: all 5 weight tensors -> single fp16 plane, ONE launch
// ---------------------------------------------------------------------------
__global__ __launch_bounds__(256)
void cvtw_all_k(const float* __restrict__ spt, const float* __restrict__ inp,
                const float* __restrict__ outp, const float* __restrict__ f1,
                const float* __restrict__ f2, __half* __restrict__ h)
{
    size_t i = ((size_t)blockIdx.x * 256 + threadIdx.x) * 4;
    if (i >= WTOT) return;
    const float* src;
    size_t off;
    if (i < WOFF_INP)       { src = spt;  off = i - WOFF_SPT;  }
    else if (i < WOFF_OUTP) { src = inp;  off = i - WOFF_INP;  }
    else if (i < WOFF_FF1)  { src = outp; off = i - WOFF_OUTP; }
    else if (i < WOFF_FF2)  { src = f1;   off = i - WOFF_FF1;  }
    else                    { src = f2;   off = i - WOFF_FF2;  }
    float4 v = *reinterpret_cast<const float4*>(src + off);
    *reinterpret_cast<uint2*>(h + i) = cvt4h(v);
}

// ---------------------------------------------------------------------------
// cls row init: x[b,0,:] = cls_token + pos_emb[0]
// ---------------------------------------------------------------------------
__global__ void cls_k(const float* __restrict__ cls_token,
                      const float* __restrict__ pos,
                      float* __restrict__ x)
{
    int i = blockIdx.x * blockDim.x + threadIdx.x;
    if (i >= BATCH * DMODEL) return;
    int b = i / DMODEL, d = i - b * DMODEL;
    x[(long)b * TTOK * DMODEL + d] = cls_token[d] + pos[d];
}

// ---------------------------------------------------------------------------
// HMMA GEMM, fp16 2-pass (A hi/lo, B plain fp16), cp.async 3-stage pipeline.
// CTA tile 128x128, K-chunk 32, 4 warps (2m x 2n), warp tile 64x64, 2 CTAs/SM.
// ---------------------------------------------------------------------------
#define EPI_STORE       0   // feat fp32
#define EPI_EMBED       1   // scatter + bias + pos
#define EPI_RESID       2   // C += acc (rmw)
#define EPI_GELU_PLANES 3   // fp16 hi/lo planes of gelu(acc+bias)
#define EPI_BIAS_RESID  4   // C += acc + bias (rmw)

#define NTHREADS 128
#define APITCH 80
#define BPITCH 272
#define OFF_AH 0
#define OFF_AL 10240
#define OFF_BH 20480
#define SBUF   29184        // 20480 + 32*272
#define STAGES 3
#define SMTOT  (STAGES*SBUF)   // 87552; x2 CTAs = 175104 < 228KB

__device__ __forceinline__ void stage_load(uint32_t sb,
                                           const __half* __restrict__ Ah,
                                           const __half* __restrict__ Al,
                                           const __half* __restrict__ Bh,
                                           int M, int N, int lda,
                                           int rowBase, int colBase, int s, int tid)
{
    const int k0 = s << 5;
    // A: 128 rows x 64B per plane; 1 row per thread, 4 x 16B segs, 2 planes
    {
        int row = tid;
        int gr  = rowBase + row;
        uint32_t nbytes = (gr < M) ? 16u : 0u;
        int grs = (gr < M) ? gr : (M - 1);
        size_t gbase = (size_t)grs * lda + k0;
        uint32_t sbase = (uint32_t)(row * APITCH);
        #pragma unroll
        for (int seg = 0; seg < 4; seg++) {
            cpasync16(sb + OFF_AH + sbase + seg * 16, Ah + gbase + seg * 8, nbytes);
            cpasync16(sb + OFF_AL + sbase + seg * 16, Al + gbase + seg * 8, nbytes);
        }
    }
    // B: 32 rows x 256B, one plane; 512 16B chunks / 128 threads = 4 each
    #pragma unroll
    for (int i = 0; i < 4; i++) {
        int idx = tid + i * 128;
        int row = idx >> 4;
        int seg = idx & 15;
        size_t goff = (size_t)(k0 + row) * N + colBase + seg * 8;
        uint32_t so = (uint32_t)(row * BPITCH + seg * 16);
        cpasync16(sb + OFF_BH + so, Bh + goff, 16u);
    }
}

__device__ __forceinline__ void compute_chunk(uint32_t sbuf, int lane, int wm, int wn,
                                              float acc[4][8][4])
{
    #pragma unroll
    for (int k16 = 0; k16 < 32; k16 += 16) {
        uint32_t aH[4][4], aL[4][4], bH[4][4];
        const uint32_t arow = (uint32_t)(wm + (lane & 7) + (lane & 8));
        const uint32_t aoff = arow * APITCH + (uint32_t)(k16 + ((lane & 16) >> 1)) * 2;
        #pragma unroll
        for (int mb = 0; mb < 4; mb++) {
            ldsm4(aH[mb], sbuf + OFF_AH + aoff + mb * 16 * APITCH);
            ldsm4(aL[mb], sbuf + OFF_AL + aoff + mb * 16 * APITCH);
        }
        const uint32_t brow = (uint32_t)(k16 + (lane & 7) + ((lane & 16) >> 1));
        const uint32_t boff = brow * BPITCH + (uint32_t)(wn + (lane & 8)) * 2;
        #pragma unroll
        for (int nb2 = 0; nb2 < 4; nb2++)
            ldsm4t(bH[nb2], sbuf + OFF_BH + boff + nb2 * 32);
        #pragma unroll
        for (int mb = 0; mb < 4; mb++) {
            #pragma unroll
            for (int nb = 0; nb < 8; nb++) {
                uint32_t bh[2] = { bH[nb >> 1][nb & 1], bH[nb >> 1][(nb & 1) + 2] };
                mma16816(acc[mb][nb], aH[mb], bh);
                mma16816(acc[mb][nb], aL[mb], bh);
            }
        }
    }
}

template<int EPI>
__global__ __launch_bounds__(NTHREADS, 2)
void mmagemm_k(const __half* __restrict__ Ah, const __half* __restrict__ Al,
               const __half* __restrict__ Bh,
               void* __restrict__ Cv, void* __restrict__ C2v,
               const float* __restrict__ bias, const float* __restrict__ extra,
               int M, int N, int K)
{
    extern __shared__ char smem[];
    const uint32_t sbase = smem_u32(smem);
    const int tid  = threadIdx.x;
    const int lane = tid & 31;
    const int wid  = tid >> 5;
    const int wm   = (wid >> 1) * 64;
    const int wn   = (wid & 1) * 64;
    const int rowBase = blockIdx.y * 128;
    const int colBase = blockIdx.x * 128;
    const int nc = K >> 5;

    float acc[4][8][4];
    #pragma unroll
    for (int a = 0; a < 4; a++)
        #pragma unroll
        for (int b = 0; b < 8; b++)
            #pragma unroll
            for (int c = 0; c < 4; c++) acc[a][b][c] = 0.f;

    #pragma unroll
    for (int s = 0; s < STAGES - 1; s++) {
        if (s < nc)
            stage_load(sbase + s * SBUF, Ah, Al, Bh, M, N, K, rowBase, colBase, s, tid);
        cp_commit();
    }

    for (int c = 0; c < nc; c++) {
        cp_wait<STAGES - 2>();
        __syncthreads();
        int s = c + STAGES - 1;
        if (s < nc)
            stage_load(sbase + (s % STAGES) * SBUF, Ah, Al, Bh, M, N, K,
                       rowBase, colBase, s, tid);
        cp_commit();
        compute_chunk(sbase + (c % STAGES) * SBUF, lane, wm, wn, acc);
    }

    // ---- epilogue ----
    const int mrow = rowBase + wm + (lane >> 2);
    const int mcol = colBase + wn + ((lane & 3) << 1);
    #pragma unroll
    for (int mi = 0; mi < 4; mi++) {
        #pragma unroll
        for (int hf = 0; hf < 2; hf++) {
            const int row = mrow + mi * 16 + hf * 8;
            if (row >= M) continue;
            #pragma unroll
            for (int ni = 0; ni < 8; ni++) {
                const int col = mcol + ni * 8;
                float v0 = acc[mi][ni][hf * 2];
                float v1 = acc[mi][ni][hf * 2 + 1];
                if (EPI == EPI_STORE) {
                    float* C = (float*)Cv;
                    *reinterpret_cast<float2*>(C + (size_t)row * N + col) =
                        make_float2(v0, v1);
                } else if (EPI == EPI_EMBED) {
                    float* C = (float*)Cv;
                    int b  = row >> 8;
                    int tl = row & 255;
                    float2 bb = *reinterpret_cast<const float2*>(bias + col);
                    float2 pp = *reinterpret_cast<const float2*>(extra + (size_t)(tl + 1) * N + col);
                    *reinterpret_cast<float2*>(C + ((size_t)b * TTOK + 1 + tl) * N + col) =
                        make_float2(v0 + bb.x + pp.x, v1 + bb.y + pp.y);
                } else if (EPI == EPI_RESID) {
                    float* C = (float*)Cv;
                    float2* o = reinterpret_cast<float2*>(C + (size_t)row * N + col);
                    float2 cc = *o;
                    *o = make_float2(cc.x + v0, cc.y + v1);
                } else if (EPI == EPI_GELU_PLANES) {
                    __half* Hh = (__half*)Cv;
                    __half* Hl = (__half*)C2v;
                    float2 bb = *reinterpret_cast<const float2*>(bias + col);
                    float g0 = gelu_exact(v0 + bb.x);
                    float g1 = gelu_exact(v1 + bb.y);
                    uint32_t h0,l0,h1,l1;
                    f2h2(g0, h0, l0); f2h2(g1, h1, l1);
                    size_t off = (size_t)row * N + col;
                    *reinterpret_cast<uint32_t*>(Hh + off) = h0 | (h1 << 16);
                    *reinterpret_cast<uint32_t*>(Hl + off) = l0 | (l1 << 16);
                } else if (EPI == EPI_BIAS_RESID) {
                    float* C = (float*)Cv;
                    float2 bb = *reinterpret_cast<const float2*>(bias + col);
                    float2* o = reinterpret_cast<float2*>(C + (size_t)row * N + col);
                    float2 cc = *o;
                    *o = make_float2(cc.x + v0 + bb.x, cc.y + v1 + bb.y);
                }
            }
        }
    }
}

// ---------------------------------------------------------------------------
// Shifted-patch extraction + LayerNorm -> fp16 hi/lo planes
// ---------------------------------------------------------------------------
__global__ __launch_bounds__(256)
void patchln_k(const float* __restrict__ img,
               const float* __restrict__ ln_g,
               const float* __restrict__ ln_b,
               __half* __restrict__ ph, __half* __restrict__ pl)
{
    const int blk = blockIdx.x;
    const int b   = blk >> 8;
    const int pt  = blk & 255;
    const int phh = pt >> 4;
    const int pw  = pt & 15;

    __shared__ float vals[PD];

    const int sh_tab[5] = {0, 0, 0, 1, -1};
    const int sw_tab[5] = {0, 1, -1, 0, 0};

    float s = 0.f, ss = 0.f;
    for (int f = threadIdx.x; f < PD; f += 256) {
        int py  = f / (PSZ * C5);
        int rem = f - py * (PSZ * C5);
        int px  = rem / C5;
        int c   = rem - px * C5;
        int g   = c / CIN;
        int ch  = c - g * CIN;
        int row = phh * PSZ + py - sh_tab[g];
        int col = pw * PSZ + px - sw_tab[g];
        float v = 0.f;
        if (row >= 0 && row < IMG && col >= 0 && col < IMG)
            v = img[(((long)b * CIN + ch) * IMG + row) * IMG + col];
        vals[f] = v;
        s  += v;
        ss += v * v;
    }
    float tsum  = blockReduceSum(s);
    float tsum2 = blockReduceSum(ss);
    float mean  = tsum * (1.f / PD);
    float var   = tsum2 * (1.f / PD) - mean * mean;
    float rstd  = rsqrtf(var + 1e-5f);
    __syncthreads();
    size_t rowoff = (size_t)blk * PD;
    for (int f = threadIdx.x; f < PD; f += 256) {
        float y = (vals[f] - mean) * rstd * ln_g[f] + ln_b[f];
        uint32_t hh, ll;
        f2h2(y, hh, ll);
        ph[rowoff + f] = __ushort_as_half((unsigned short)hh);
        pl[rowoff + f] = __ushort_as_half((unsigned short)ll);
    }
}

// ---------------------------------------------------------------------------
__global__ void lb_k(const float* __restrict__ lbin, float* __restrict__ lbout)
{
    int d = blockIdx.x * blockDim.x + threadIdx.x;
    if (d >= DMODEL) return;
    float v[DEPTH];
    float m = -1e30f;
    #pragma unroll
    for (int i = 0; i < DEPTH; i++) { v[i] = lbin[i * DMODEL + d]; m = fmaxf(m, v[i]); }
    float s = 0.f;
    #pragma unroll
    for (int i = 0; i < DEPTH; i++) { v[i] = expf(v[i] - m); s += v[i]; }
    float inv = 1.f / s;
    float c = 0.f;
    float c0 = v[0] * inv;
    #pragma unroll
    for (int i = 0; i < DEPTH; i++) { c += v[i] * inv; lbout[i * DMODEL + d] = c - c0; }
}

// RMSNorm -> fp16 hi/lo planes
__global__ __launch_bounds__(256)
void rmsnorm_k(const float* __restrict__ x,
               __half* __restrict__ yh, __half* __restrict__ yl)
{
    const long row = blockIdx.x;
    const float* xr = x + row * DMODEL;
    float s = 0.f;
    for (int i = threadIdx.x; i < DMODEL; i += 256) { float v = xr[i]; s += v * v; }
    float tot = blockReduceSum(s);
    float r = rsqrtf(tot * (1.f / DMODEL) + 1e-6f);
    size_t off = (size_t)row * DMODEL;
    for (int i = threadIdx.x; i < DMODEL; i += 256) {
        uint32_t hh, ll;
        f2h2(xr[i] * r, hh, ll);
        yh[off + i] = __ushort_as_half((unsigned short)hh);
        yl[off + i] = __ushort_as_half((unsigned short)ll);
    }
}

// hGRU2 scan -> fp16 hi/lo planes
__global__ __launch_bounds__(256)
void hgru_k(const float* __restrict__ feat, const float* __restrict__ lb,
            __half* __restrict__ oh, __half* __restrict__ ol)
{
    int e = blockIdx.x * blockDim.x + threadIdx.x;
    if (e >= TTOK * NHEAD) return;
    int t = e / NHEAD;
    int h = e - t * NHEAD;

    float lb0 = lb[2 * h];
    float lb1 = lb[2 * h + 1];
    float S00 = 0.f, S01 = 0.f, S10 = 0.f, S11 = 0.f;

    #pragma unroll 1
    for (int n = 0; n < BATCH; n++) {
        const float* r = feat + (long)(n * TTOK + t) * (3 * DMODEL);
        float2 vv = *(const float2*)(r + 2 * h);
        float2 qq = *(const float2*)(r + DMODEL + 2 * h);
        float2 ff = *(const float2*)(r + 2 * DMODEL + 2 * h);
        float v0 = gelu_exact(vv.x), v1 = gelu_exact(vv.y);
        float q0 = gelu_exact(qq.x), q1 = gelu_exact(qq.y);
        float s0 = 1.f / (1.f + expf(-ff.x));
        float s1 = 1.f / (1.f + expf(-ff.y));
        float lam0 = lb0 + (1.f - lb0) * s0;
        float lam1 = lb1 + (1.f - lb1) * s1;
        float k0 = 1.f - lam0, k1 = 1.f - lam1;
        S00 = lam0 * S00 + k0 * v0;  S01 = lam0 * S01 + k0 * v1;
        S10 = lam1 * S10 + k1 * v0;  S11 = lam1 * S11 + k1 * v1;
        float o0 = q0 * S00 + q1 * S10;
        float o1 = q0 * S01 + q1 * S11;
        uint32_t h0,l0,h1,l1;
        f2h2(o0, h0, l0); f2h2(o1, h1, l1);
        size_t off = (size_t)(n * TTOK + t) * DMODEL + 2 * h;
        *reinterpret_cast<uint32_t*>(oh + off) = h0 | (h1 << 16);
        *reinterpret_cast<uint32_t*>(ol + off) = l0 | (l1 << 16);
    }
}

__global__ __launch_bounds__(256)
void final_k(const float* __restrict__ x,
             const float* __restrict__ g, const float* __restrict__ bvec,
             float* __restrict__ cls)
{
    int b = blockIdx.x;
    const float* xr = x + (long)b * TTOK * DMODEL;
    __shared__ float y[DMODEL];
    float s = 0.f, ss = 0.f;
    for (int i = threadIdx.x; i < DMODEL; i += 256) {
        float v = xr[i];
        y[i] = v;
        s  += v;
        ss += v * v;
    }
    float tsum  = blockReduceSum(s);
    float tsum2 = blockReduceSum(ss);
    float rstd1 = rsqrtf(tsum2 * (1.f / DMODEL) + 1e-6f);
    float mean  = rstd1 * tsum * (1.f / DMODEL);
    float ez2   = rstd1 * rstd1 * tsum2 * (1.f / DMODEL);
    float var   = ez2 - mean * mean;
    float rstd2 = rsqrtf(var + 1e-5f);
    __syncthreads();
    for (int i = threadIdx.x; i < DMODEL; i += 256) {
        float z = y[i] * rstd1;
        cls[(long)b * DMODEL + i] = (z - mean) * rstd2 * g[i] + bvec[i];
    }
}

__global__ __launch_bounds__(256)
void head_k(const float* __restrict__ cls, const float* __restrict__ w,
            const float* __restrict__ bias, float* __restrict__ out)
{
    int idx = blockIdx.x * blockDim.x + threadIdx.x;
    if (idx >= BATCH * NCLS) return;
    int b = idx / NCLS, c = idx - b * NCLS;
    const float* xr = cls + (long)b * DMODEL;
    float s = bias[c];
    #pragma unroll 4
    for (int k = 0; k < DMODEL; k++)
        s = fmaf(xr[k], w[(long)k * NCLS + c], s);
    out[idx] = s;
}

// ---------------------------------------------------------------------------
// Launch
// ---------------------------------------------------------------------------
extern "C" void kernel_launch(void* const* d_in, const int* in_sizes, int n_in,
                              void* d_out, int out_size)
{
    const float* img          = (const float*)d_in[0];
    const float* spt_ln_g     = (const float*)d_in[1];
    const float* spt_ln_b     = (const float*)d_in[2];
    const float* spt_w        = (const float*)d_in[3];
    const float* spt_b        = (const float*)d_in[4];
    const float* pos_emb      = (const float*)d_in[5];
    const float* cls_token    = (const float*)d_in[6];
    const float* lower_bounds = (const float*)d_in[7];
    const float* in_proj_w    = (const float*)d_in[8];
    const float* out_proj_w   = (const float*)d_in[9];
    const float* ff_w1        = (const float*)d_in[10];
    const float* ff_b1        = (const float*)d_in[11];
    const float* ff_w2        = (const float*)d_in[12];
    const float* ff_b2        = (const float*)d_in[13];
    const float* head_ln_g    = (const float*)d_in[14];
    const float* head_ln_b    = (const float*)d_in[15];
    const float* head_w       = (const float*)d_in[16];
    const float* head_b       = (const float*)d_in[17];

    __half *wh, *ph, *pl, *xnh, *xnl, *oh, *ol, *hmh, *hml;
    float *x, *feat, *lb, *cls;
    cudaGetSymbolAddress((void**)&wh,   g_wh);
    cudaGetSymbolAddress((void**)&ph,   g_ph);
    cudaGetSymbolAddress((void**)&pl,   g_pl);
    cudaGetSymbolAddress((void**)&xnh,  g_xnh);
    cudaGetSymbolAddress((void**)&xnl,  g_xnl);
    cudaGetSymbolAddress((void**)&oh,   g_oh);
    cudaGetSymbolAddress((void**)&ol,   g_ol);
    cudaGetSymbolAddress((void**)&hmh,  g_hmh);
    cudaGetSymbolAddress((void**)&hml,  g_hml);
    cudaGetSymbolAddress((void**)&x,    g_x);
    cudaGetSymbolAddress((void**)&feat, g_feat);
    cudaGetSymbolAddress((void**)&lb,   g_lb);
    cudaGetSymbolAddress((void**)&cls,  g_cls);

    static bool attr_done = false;
    if (!attr_done) {
        cudaFuncSetAttribute(mmagemm_k<EPI_STORE>,       cudaFuncAttributeMaxDynamicSharedMemorySize, SMTOT);
        cudaFuncSetAttribute(mmagemm_k<EPI_EMBED>,       cudaFuncAttributeMaxDynamicSharedMemorySize, SMTOT);
        cudaFuncSetAttribute(mmagemm_k<EPI_RESID>,       cudaFuncAttributeMaxDynamicSharedMemorySize, SMTOT);
        cudaFuncSetAttribute(mmagemm_k<EPI_GELU_PLANES>, cudaFuncAttributeMaxDynamicSharedMemorySize, SMTOT);
        cudaFuncSetAttribute(mmagemm_k<EPI_BIAS_RESID>,  cudaFuncAttributeMaxDynamicSharedMemorySize, SMTOT);
        attr_done = true;
    }

    patchln_k<<<NROWS_EMBED, 256>>>(img, spt_ln_g, spt_ln_b, ph, pl);
    cvtw_all_k<<<(int)((WTOT / 4 + 255) / 256), 256>>>(spt_w, in_proj_w, out_proj_w,
                                                       ff_w1, ff_w2, wh);
    cls_k<<<(BATCH * DMODEL + 255) / 256, 256>>>(cls_token, pos_emb, x);
    {
        dim3 grid(DMODEL / 128, NROWS_EMBED / 128);
        mmagemm_k<EPI_EMBED><<<grid, NTHREADS, SMTOT>>>(
            ph, pl, wh + WOFF_SPT,
            x, nullptr, spt_b, pos_emb, NROWS_EMBED, DMODEL, PD);
    }
    lb_k<<<(DMODEL + 255) / 256, 256>>>(lower_bounds, lb);

    for (int i = 0; i < DEPTH; i++) {
        rmsnorm_k<<<NT, 256>>>(x, xnh, xnl);
        {
            dim3 grid((3 * DMODEL) / 128, (NT + 127) / 128);
            mmagemm_k<EPI_STORE><<<grid, NTHREADS, SMTOT>>>(
                xnh, xnl,
                wh + WOFF_INP + (size_t)i * DMODEL * 3 * DMODEL,
                feat, nullptr, nullptr, nullptr, NT, 3 * DMODEL, DMODEL);
        }
        hgru_k<<<(TTOK * NHEAD + 255) / 256, 256>>>(feat, lb + (size_t)i * DMODEL, oh, ol);
        {
            dim3 grid(DMODEL / 128, (NT + 127) / 128);
            mmagemm_k<EPI_RESID><<<grid, NTHREADS, SMTOT>>>(
                oh, ol,
                wh + WOFF_OUTP + (size_t)i * DMODEL * DMODEL,
                x, nullptr, nullptr, nullptr, NT, DMODEL, DMODEL);
        }
        rmsnorm_k<<<NT, 256>>>(x, xnh, xnl);
        {
            dim3 grid(MLP / 128, (NT + 127) / 128);
            mmagemm_k<EPI_GELU_PLANES><<<grid, NTHREADS, SMTOT>>>(
                xnh, xnl,
                wh + WOFF_FF1 + (size_t)i * DMODEL * MLP,
                hmh, hml, ff_b1 + (size_t)i * MLP, nullptr, NT, MLP, DMODEL);
        }
        {
            dim3 grid(DMODEL / 128, (NT + 127) / 128);
            mmagemm_k<EPI_BIAS_RESID><<<grid, NTHREADS, SMTOT>>>(
                hmh, hml,
                wh + WOFF_FF2 + (size_t)i * MLP * DMODEL,
                x, nullptr, ff_b2 + (size_t)i * DMODEL, nullptr, NT, DMODEL, MLP);
        }
    }

    final_k<<<BATCH, 256>>>(x, head_ln_g, head_ln_b, cls);
    head_k<<<(BATCH * NCLS + 255) / 256, 256>>>(cls, head_w, head_b, (float*)d_out);
}

// round 8
// speedup vs baseline: 1.3165x; 1.1625x over previous
#include <cuda_runtime.h>
#include <cuda_fp16.h>
#include <math.h>
#include <stdint.h>

// ---------------------------------------------------------------------------
// Problem constants
// ---------------------------------------------------------------------------
#define BATCH   16
#define CIN     3
#define IMG     256
#define PSZ     16
#define NPATCH  256
#define C5      15
#define PD      3840
#define DMODEL  768
#define DEPTH   8
#define MLP     3072
#define NCLS    1000
#define TTOK    257
#define NT      (BATCH*TTOK)        // 4112
#define NROWS_EMBED (BATCH*NPATCH)  // 4096
#define NHEAD   384

// weight plane offsets (elements)
#define WOFF_SPT  0
#define WSZ_SPT   (PD*DMODEL)
#define WOFF_INP  (WOFF_SPT + WSZ_SPT)
#define WSZ_INP   (DEPTH*DMODEL*3*DMODEL)
#define WOFF_OUTP (WOFF_INP + WSZ_INP)
#define WSZ_OUTP  (DEPTH*DMODEL*DMODEL)
#define WOFF_FF1  (WOFF_OUTP + WSZ_OUTP)
#define WSZ_FF1   (DEPTH*DMODEL*MLP)
#define WOFF_FF2  (WOFF_FF1 + WSZ_FF1)
#define WSZ_FF2   (DEPTH*MLP*DMODEL)
#define WTOT      (WOFF_FF2 + WSZ_FF2)

// ---------------------------------------------------------------------------
// Scratch (device globals)
// ---------------------------------------------------------------------------
__device__ __half g_wh[WTOT];                 // weights: single fp16 plane
__device__ __half g_ph[NROWS_EMBED * PD];     // activations: hi/lo fp16 planes
__device__ __half g_pl[NROWS_EMBED * PD];
__device__ __half g_xnh[NT * DMODEL];
__device__ __half g_xnl[NT * DMODEL];
__device__ __half g_oh[NT * DMODEL];
__device__ __half g_ol[NT * DMODEL];
__device__ __half g_hmh[NT * MLP];
__device__ __half g_hml[NT * MLP];
__device__ float g_x[NT * DMODEL];
__device__ float g_feat[NT * 3 * DMODEL];
__device__ float g_lb[DEPTH * DMODEL];
__device__ float g_cls[BATCH * DMODEL];

// ---------------------------------------------------------------------------
// Helpers
// ---------------------------------------------------------------------------
__device__ __forceinline__ uint32_t smem_u32(const void* p) {
    uint32_t a;
    asm("{ .reg .u64 t; cvta.to.shared.u64 t, %1; cvt.u32.u64 %0, t; }"
        : "=r"(a) : "l"(p));
    return a;
}
__device__ __forceinline__ void ldsm4(uint32_t* r, uint32_t addr) {
    asm volatile("ldmatrix.sync.aligned.m8n8.x4.shared.b16 {%0,%1,%2,%3}, [%4];"
                 : "=r"(r[0]), "=r"(r[1]), "=r"(r[2]), "=r"(r[3]) : "r"(addr));
}
__device__ __forceinline__ void ldsm4t(uint32_t* r, uint32_t addr) {
    asm volatile("ldmatrix.sync.aligned.m8n8.x4.trans.shared.b16 {%0,%1,%2,%3}, [%4];"
                 : "=r"(r[0]), "=r"(r[1]), "=r"(r[2]), "=r"(r[3]) : "r"(addr));
}
__device__ __forceinline__ void mma16816(float* d, const uint32_t* a, const uint32_t* b) {
    asm volatile(
        "mma.sync.aligned.m16n8k16.row.col.f32.f16.f16.f32 "
        "{%0,%1,%2,%3}, {%4,%5,%6,%7}, {%8,%9}, {%0,%1,%2,%3};"
        : "+f"(d[0]), "+f"(d[1]), "+f"(d[2]), "+f"(d[3])
        : "r"(a[0]), "r"(a[1]), "r"(a[2]), "r"(a[3]), "r"(b[0]), "r"(b[1]));
}
__device__ __forceinline__ void cpasync16(uint32_t dst, const void* src, uint32_t n) {
    asm volatile("cp.async.cg.shared.global [%0], [%1], 16, %2;"
                 :: "r"(dst), "l"(src), "r"(n) : "memory");
}
__device__ __forceinline__ void cp_commit() {
    asm volatile("cp.async.commit_group;" ::: "memory");
}
template<int N>
__device__ __forceinline__ void cp_wait() {
    asm volatile("cp.async.wait_group %0;" :: "n"(N) : "memory");
}

__device__ __forceinline__ float gelu_exact(float x) {
    return 0.5f * x * (1.f + erff(x * 0.70710678118654752440f));
}

__device__ __forceinline__ float blockReduceSum(float v) {
    __shared__ float sh[32];
    __shared__ float res;
    int lane = threadIdx.x & 31;
    int wid  = threadIdx.x >> 5;
    #pragma unroll
    for (int o = 16; o > 0; o >>= 1) v += __shfl_down_sync(0xffffffffu, v, o);
    if (lane == 0) sh[wid] = v;
    __syncthreads();
    int nw = (blockDim.x + 31) >> 5;
    v = (threadIdx.x < nw) ? sh[threadIdx.x] : 0.f;
    if (wid == 0) {
        #pragma unroll
        for (int o = 16; o > 0; o >>= 1) v += __shfl_down_sync(0xffffffffu, v, o);
        if (lane == 0) res = v;
    }
    __syncthreads();
    return res;
}

// fp32 -> (hi, lo) fp16
__device__ __forceinline__ void f2h2(float v, uint32_t& h, uint32_t& l) {
    __half hh = __float2half_rn(v);
    float r = v - __half2float(hh);
    __half ll = __float2half_rn(r);
    h = (uint32_t)__half_as_ushort(hh);
    l = (uint32_t)__half_as_ushort(ll);
}
__device__ __forceinline__ uint2 cvt4h(float4 v) {
    __half2 a = __floats2half2_rn(v.x, v.y);
    __half2 b = __floats2half2_rn(v.z, v.w);
    return make_uint2(*reinterpret_cast<uint32_t*>(&a), *reinterpret_cast<uint32_t*>(&b));
}

// ---------------------------------------------------------------------------
// Weight pre-conversion: all 5 weight tensors -> single fp16 plane, ONE launch
// ---------------------------------------------------------------------------
__global__ __launch_bounds__(256)
void cvtw_all_k(const float* __restrict__ spt, const float* __restrict__ inp,
                const float* __restrict__ outp, const float* __restrict__ f1,
                const float* __restrict__ f2, __half* __restrict__ h)
{
    size_t i = ((size_t)blockIdx.x * 256 + threadIdx.x) * 4;
    if (i >= WTOT) return;
    const float* src;
    size_t off;
    if (i < WOFF_INP)       { src = spt;  off = i - WOFF_SPT;  }
    else if (i < WOFF_OUTP) { src = inp;  off = i - WOFF_INP;  }
    else if (i < WOFF_FF1)  { src = outp; off = i - WOFF_OUTP; }
    else if (i < WOFF_FF2)  { src = f1;   off = i - WOFF_FF1;  }
    else                    { src = f2;   off = i - WOFF_FF2;  }
    float4 v = *reinterpret_cast<const float4*>(src + off);
    *reinterpret_cast<uint2*>(h + i) = cvt4h(v);
}

// ---------------------------------------------------------------------------
// cls row init
// ---------------------------------------------------------------------------
__global__ void cls_k(const float* __restrict__ cls_token,
                      const float* __restrict__ pos,
                      float* __restrict__ x)
{
    int i = blockIdx.x * blockDim.x + threadIdx.x;
    if (i >= BATCH * DMODEL) return;
    int b = i / DMODEL, d = i - b * DMODEL;
    x[(long)b * TTOK * DMODEL + d] = cls_token[d] + pos[d];
}

// ---------------------------------------------------------------------------
// HMMA GEMM, fp16 2-pass (A hi/lo, B plain fp16), cp.async 3-stage pipeline.
// CTA tile 128x128, K-chunk 32, 8 warps (2m x 4n), warp tile 64x32, 2 CTAs/SM.
// ---------------------------------------------------------------------------
#define EPI_STORE       0
#define EPI_EMBED       1
#define EPI_RESID       2
#define EPI_GELU_PLANES 3
#define EPI_BIAS_RESID  4

#define NTHREADS 256
#define APITCH 80
#define BPITCH 272
#define OFF_AH 0
#define OFF_AL 10240
#define OFF_BH 20480
#define SBUF   29184        // 20480 + 32*272
#define STAGES 3
#define SMTOT  (STAGES*SBUF)   // 87552; x2 CTAs = 175104 < 228KB

__device__ __forceinline__ void stage_load(uint32_t sb,
                                           const __half* __restrict__ Ah,
                                           const __half* __restrict__ Al,
                                           const __half* __restrict__ Bh,
                                           int M, int N, int lda,
                                           int rowBase, int colBase, int s, int tid)
{
    const int k0 = s << 5;
    // A: 128 rows x 64B per plane, 2 planes; 2 chunks per thread per plane
    {
        int row  = tid >> 1;
        int half = tid & 1;              // 0 -> bytes [0,32), 1 -> [32,64)
        int gr   = rowBase + row;
        uint32_t nbytes = (gr < M) ? 16u : 0u;
        int grs = (gr < M) ? gr : (M - 1);
        size_t gbase = (size_t)grs * lda + k0 + half * 16;
        uint32_t sbase = (uint32_t)(row * APITCH + half * 32);
        cpasync16(sb + OFF_AH + sbase,      Ah + gbase,     nbytes);
        cpasync16(sb + OFF_AH + sbase + 16, Ah + gbase + 8, nbytes);
        cpasync16(sb + OFF_AL + sbase,      Al + gbase,     nbytes);
        cpasync16(sb + OFF_AL + sbase + 16, Al + gbase + 8, nbytes);
    }
    // B: 32 rows x 256B, one plane; 512 chunks / 256 threads = 2 each
    #pragma unroll
    for (int i = 0; i < 2; i++) {
        int idx = tid + i * 256;
        int row = idx >> 4;
        int seg = idx & 15;
        size_t goff = (size_t)(k0 + row) * N + colBase + seg * 8;
        uint32_t so = (uint32_t)(row * BPITCH + seg * 16);
        cpasync16(sb + OFF_BH + so, Bh + goff, 16u);
    }
}

__device__ __forceinline__ void compute_chunk(uint32_t sbuf, int lane, int wm, int wn,
                                              float acc[4][4][4])
{
    #pragma unroll
    for (int k16 = 0; k16 < 32; k16 += 16) {
        const uint32_t arow = (uint32_t)(wm + (lane & 7) + (lane & 8));
        const uint32_t aoff = arow * APITCH + (uint32_t)(k16 + ((lane & 16) >> 1)) * 2;
        const uint32_t brow = (uint32_t)(k16 + (lane & 7) + ((lane & 16) >> 1));
        const uint32_t boff = brow * BPITCH + (uint32_t)(wn + (lane & 8)) * 2;

        uint32_t bH[2][4];
        #pragma unroll
        for (int nb2 = 0; nb2 < 2; nb2++)
            ldsm4t(bH[nb2], sbuf + OFF_BH + boff + nb2 * 32);

        // pass H
        #pragma unroll
        for (int mb = 0; mb < 4; mb++) {
            uint32_t a[4];
            ldsm4(a, sbuf + OFF_AH + aoff + mb * 16 * APITCH);
            #pragma unroll
            for (int nb = 0; nb < 4; nb++) {
                uint32_t bb[2] = { bH[nb >> 1][nb & 1], bH[nb >> 1][(nb & 1) + 2] };
                mma16816(acc[mb][nb], a, bb);
            }
        }
        // pass L
        #pragma unroll
        for (int mb = 0; mb < 4; mb++) {
            uint32_t a[4];
            ldsm4(a, sbuf + OFF_AL + aoff + mb * 16 * APITCH);
            #pragma unroll
            for (int nb = 0; nb < 4; nb++) {
                uint32_t bb[2] = { bH[nb >> 1][nb & 1], bH[nb >> 1][(nb & 1) + 2] };
                mma16816(acc[mb][nb], a, bb);
            }
        }
    }
}

template<int EPI>
__global__ __launch_bounds__(NTHREADS, 2)
void mmagemm_k(const __half* __restrict__ Ah, const __half* __restrict__ Al,
               const __half* __restrict__ Bh,
               void* __restrict__ Cv, void* __restrict__ C2v,
               const float* __restrict__ bias, const float* __restrict__ extra,
               int M, int N, int K)
{
    extern __shared__ char smem[];
    const uint32_t sbase = smem_u32(smem);
    const int tid  = threadIdx.x;
    const int lane = tid & 31;
    const int wid  = tid >> 5;
    const int wm   = (wid >> 2) * 64;   // 2 m-warps
    const int wn   = (wid & 3) * 32;    // 4 n-warps
    const int rowBase = blockIdx.y * 128;
    const int colBase = blockIdx.x * 128;
    const int nc = K >> 5;

    float acc[4][4][4];
    #pragma unroll
    for (int a = 0; a < 4; a++)
        #pragma unroll
        for (int b = 0; b < 4; b++)
            #pragma unroll
            for (int c = 0; c < 4; c++) acc[a][b][c] = 0.f;

    #pragma unroll
    for (int s = 0; s < STAGES - 1; s++) {
        if (s < nc)
            stage_load(sbase + s * SBUF, Ah, Al, Bh, M, N, K, rowBase, colBase, s, tid);
        cp_commit();
    }

    for (int c = 0; c < nc; c++) {
        cp_wait<STAGES - 2>();
        __syncthreads();
        int s = c + STAGES - 1;
        if (s < nc)
            stage_load(sbase + (s % STAGES) * SBUF, Ah, Al, Bh, M, N, K,
                       rowBase, colBase, s, tid);
        cp_commit();
        compute_chunk(sbase + (c % STAGES) * SBUF, lane, wm, wn, acc);
    }

    // ---- epilogue ----
    const int mrow = rowBase + wm + (lane >> 2);
    const int mcol = colBase + wn + ((lane & 3) << 1);
    #pragma unroll
    for (int mi = 0; mi < 4; mi++) {
        #pragma unroll
        for (int hf = 0; hf < 2; hf++) {
            const int row = mrow + mi * 16 + hf * 8;
            if (row >= M) continue;
            #pragma unroll
            for (int ni = 0; ni < 4; ni++) {
                const int col = mcol + ni * 8;
                float v0 = acc[mi][ni][hf * 2];
                float v1 = acc[mi][ni][hf * 2 + 1];
                if (EPI == EPI_STORE) {
                    float* C = (float*)Cv;
                    *reinterpret_cast<float2*>(C + (size_t)row * N + col) =
                        make_float2(v0, v1);
                } else if (EPI == EPI_EMBED) {
                    float* C = (float*)Cv;
                    int b  = row >> 8;
                    int tl = row & 255;
                    float2 bb = *reinterpret_cast<const float2*>(bias + col);
                    float2 pp = *reinterpret_cast<const float2*>(extra + (size_t)(tl + 1) * N + col);
                    *reinterpret_cast<float2*>(C + ((size_t)b * TTOK + 1 + tl) * N + col) =
                        make_float2(v0 + bb.x + pp.x, v1 + bb.y + pp.y);
                } else if (EPI == EPI_RESID) {
                    float* C = (float*)Cv;
                    float2* o = reinterpret_cast<float2*>(C + (size_t)row * N + col);
                    float2 cc = *o;
                    *o = make_float2(cc.x + v0, cc.y + v1);
                } else if (EPI == EPI_GELU_PLANES) {
                    __half* Hh = (__half*)Cv;
                    __half* Hl = (__half*)C2v;
                    float2 bb = *reinterpret_cast<const float2*>(bias + col);
                    float g0 = gelu_exact(v0 + bb.x);
                    float g1 = gelu_exact(v1 + bb.y);
                    uint32_t h0,l0,h1,l1;
                    f2h2(g0, h0, l0); f2h2(g1, h1, l1);
                    size_t off = (size_t)row * N + col;
                    *reinterpret_cast<uint32_t*>(Hh + off) = h0 | (h1 << 16);
                    *reinterpret_cast<uint32_t*>(Hl + off) = l0 | (l1 << 16);
                } else if (EPI == EPI_BIAS_RESID) {
                    float* C = (float*)Cv;
                    float2 bb = *reinterpret_cast<const float2*>(bias + col);
                    float2* o = reinterpret_cast<float2*>(C + (size_t)row * N + col);
                    float2 cc = *o;
                    *o = make_float2(cc.x + v0 + bb.x, cc.y + v1 + bb.y);
                }
            }
        }
    }
}

// ---------------------------------------------------------------------------
// Shifted-patch extraction + LayerNorm -> fp16 hi/lo planes
// ---------------------------------------------------------------------------
__global__ __launch_bounds__(256)
void patchln_k(const float* __restrict__ img,
               const float* __restrict__ ln_g,
               const float* __restrict__ ln_b,
               __half* __restrict__ ph, __half* __restrict__ pl)
{
    const int blk = blockIdx.x;
    const int b   = blk >> 8;
    const int pt  = blk & 255;
    const int phh = pt >> 4;
    const int pw  = pt & 15;

    __shared__ float vals[PD];

    const int sh_tab[5] = {0, 0, 0, 1, -1};
    const int sw_tab[5] = {0, 1, -1, 0, 0};

    float s = 0.f, ss = 0.f;
    for (int f = threadIdx.x; f < PD; f += 256) {
        int py  = f / (PSZ * C5);
        int rem = f - py * (PSZ * C5);
        int px  = rem / C5;
        int c   = rem - px * C5;
        int g   = c / CIN;
        int ch  = c - g * CIN;
        int row = phh * PSZ + py - sh_tab[g];
        int col = pw * PSZ + px - sw_tab[g];
        float v = 0.f;
        if (row >= 0 && row < IMG && col >= 0 && col < IMG)
            v = img[(((long)b * CIN + ch) * IMG + row) * IMG + col];
        vals[f] = v;
        s  += v;
        ss += v * v;
    }
    float tsum  = blockReduceSum(s);
    float tsum2 = blockReduceSum(ss);
    float mean  = tsum * (1.f / PD);
    float var   = tsum2 * (1.f / PD) - mean * mean;
    float rstd  = rsqrtf(var + 1e-5f);
    __syncthreads();
    size_t rowoff = (size_t)blk * PD;
    for (int f = threadIdx.x; f < PD; f += 256) {
        float y = (vals[f] - mean) * rstd * ln_g[f] + ln_b[f];
        uint32_t hh, ll;
        f2h2(y, hh, ll);
        ph[rowoff + f] = __ushort_as_half((unsigned short)hh);
        pl[rowoff + f] = __ushort_as_half((unsigned short)ll);
    }
}

// ---------------------------------------------------------------------------
__global__ void lb_k(const float* __restrict__ lbin, float* __restrict__ lbout)
{
    int d = blockIdx.x * blockDim.x + threadIdx.x;
    if (d >= DMODEL) return;
    float v[DEPTH];
    float m = -1e30f;
    #pragma unroll
    for (int i = 0; i < DEPTH; i++) { v[i] = lbin[i * DMODEL + d]; m = fmaxf(m, v[i]); }
    float s = 0.f;
    #pragma unroll
    for (int i = 0; i < DEPTH; i++) { v[i] = expf(v[i] - m); s += v[i]; }
    float inv = 1.f / s;
    float c = 0.f;
    float c0 = v[0] * inv;
    #pragma unroll
    for (int i = 0; i < DEPTH; i++) { c += v[i] * inv; lbout[i * DMODEL + d] = c - c0; }
}

// RMSNorm -> fp16 hi/lo planes
__global__ __launch_bounds__(256)
void rmsnorm_k(const float* __restrict__ x,
               __half* __restrict__ yh, __half* __restrict__ yl)
{
    const long row = blockIdx.x;
    const float* xr = x + row * DMODEL;
    float s = 0.f;
    for (int i = threadIdx.x; i < DMODEL; i += 256) { float v = xr[i]; s += v * v; }
    float tot = blockReduceSum(s);
    float r = rsqrtf(tot * (1.f / DMODEL) + 1e-6f);
    size_t off = (size_t)row * DMODEL;
    for (int i = threadIdx.x; i < DMODEL; i += 256) {
        uint32_t hh, ll;
        f2h2(xr[i] * r, hh, ll);
        yh[off + i] = __ushort_as_half((unsigned short)hh);
        yl[off + i] = __ushort_as_half((unsigned short)ll);
    }
}

// hGRU2 scan -> fp16 hi/lo planes
__global__ __launch_bounds__(256)
void hgru_k(const float* __restrict__ feat, const float* __restrict__ lb,
            __half* __restrict__ oh, __half* __restrict__ ol)
{
    int e = blockIdx.x * blockDim.x + threadIdx.x;
    if (e >= TTOK * NHEAD) return;
    int t = e / NHEAD;
    int h = e - t * NHEAD;

    float lb0 = lb[2 * h];
    float lb1 = lb[2 * h + 1];
    float S00 = 0.f, S01 = 0.f, S10 = 0.f, S11 = 0.f;

    #pragma unroll 1
    for (int n = 0; n < BATCH; n++) {
        const float* r = feat + (long)(n * TTOK + t) * (3 * DMODEL);
        float2 vv = *(const float2*)(r + 2 * h);
        float2 qq = *(const float2*)(r + DMODEL + 2 * h);
        float2 ff = *(const float2*)(r + 2 * DMODEL + 2 * h);
        float v0 = gelu_exact(vv.x), v1 = gelu_exact(vv.y);
        float q0 = gelu_exact(qq.x), q1 = gelu_exact(qq.y);
        float s0 = 1.f / (1.f + expf(-ff.x));
        float s1 = 1.f / (1.f + expf(-ff.y));
        float lam0 = lb0 + (1.f - lb0) * s0;
        float lam1 = lb1 + (1.f - lb1) * s1;
        float k0 = 1.f - lam0, k1 = 1.f - lam1;
        S00 = lam0 * S00 + k0 * v0;  S01 = lam0 * S01 + k0 * v1;
        S10 = lam1 * S10 + k1 * v0;  S11 = lam1 * S11 + k1 * v1;
        float o0 = q0 * S00 + q1 * S10;
        float o1 = q0 * S01 + q1 * S11;
        uint32_t h0,l0,h1,l1;
        f2h2(o0, h0, l0); f2h2(o1, h1, l1);
        size_t off = (size_t)(n * TTOK + t) * DMODEL + 2 * h;
        *reinterpret_cast<uint32_t*>(oh + off) = h0 | (h1 << 16);
        *reinterpret_cast<uint32_t*>(ol + off) = l0 | (l1 << 16);
    }
}

__global__ __launch_bounds__(256)
void final_k(const float* __restrict__ x,
             const float* __restrict__ g, const float* __restrict__ bvec,
             float* __restrict__ cls)
{
    int b = blockIdx.x;
    const float* xr = x + (long)b * TTOK * DMODEL;
    __shared__ float y[DMODEL];
    float s = 0.f, ss = 0.f;
    for (int i = threadIdx.x; i < DMODEL; i += 256) {
        float v = xr[i];
        y[i] = v;
        s  += v;
        ss += v * v;
    }
    float tsum  = blockReduceSum(s);
    float tsum2 = blockReduceSum(ss);
    float rstd1 = rsqrtf(tsum2 * (1.f / DMODEL) + 1e-6f);
    float mean  = rstd1 * tsum * (1.f / DMODEL);
    float ez2   = rstd1 * rstd1 * tsum2 * (1.f / DMODEL);
    float var   = ez2 - mean * mean;
    float rstd2 = rsqrtf(var + 1e-5f);
    __syncthreads();
    for (int i = threadIdx.x; i < DMODEL; i += 256) {
        float z = y[i] * rstd1;
        cls[(long)b * DMODEL + i] = (z - mean) * rstd2 * g[i] + bvec[i];
    }
}

__global__ __launch_bounds__(256)
void head_k(const float* __restrict__ cls, const float* __restrict__ w,
            const float* __restrict__ bias, float* __restrict__ out)
{
    int idx = blockIdx.x * blockDim.x + threadIdx.x;
    if (idx >= BATCH * NCLS) return;
    int b = idx / NCLS, c = idx - b * NCLS;
    const float* xr = cls + (long)b * DMODEL;
    float s = bias[c];
    #pragma unroll 4
    for (int k = 0; k < DMODEL; k++)
        s = fmaf(xr[k], w[(long)k * NCLS + c], s);
    out[idx] = s;
}

// ---------------------------------------------------------------------------
// Launch
// ---------------------------------------------------------------------------
extern "C" void kernel_launch(void* const* d_in, const int* in_sizes, int n_in,
                              void* d_out, int out_size)
{
    const float* img          = (const float*)d_in[0];
    const float* spt_ln_g     = (const float*)d_in[1];
    const float* spt_ln_b     = (const float*)d_in[2];
    const float* spt_w        = (const float*)d_in[3];
    const float* spt_b        = (const float*)d_in[4];
    const float* pos_emb      = (const float*)d_in[5];
    const float* cls_token    = (const float*)d_in[6];
    const float* lower_bounds = (const float*)d_in[7];
    const float* in_proj_w    = (const float*)d_in[8];
    const float* out_proj_w   = (const float*)d_in[9];
    const float* ff_w1        = (const float*)d_in[10];
    const float* ff_b1        = (const float*)d_in[11];
    const float* ff_w2        = (const float*)d_in[12];
    const float* ff_b2        = (const float*)d_in[13];
    const float* head_ln_g    = (const float*)d_in[14];
    const float* head_ln_b    = (const float*)d_in[15];
    const float* head_w       = (const float*)d_in[16];
    const float* head_b       = (const float*)d_in[17];

    __half *wh, *ph, *pl, *xnh, *xnl, *oh, *ol, *hmh, *hml;
    float *x, *feat, *lb, *cls;
    cudaGetSymbolAddress((void**)&wh,   g_wh);
    cudaGetSymbolAddress((void**)&ph,   g_ph);
    cudaGetSymbolAddress((void**)&pl,   g_pl);
    cudaGetSymbolAddress((void**)&xnh,  g_xnh);
    cudaGetSymbolAddress((void**)&xnl,  g_xnl);
    cudaGetSymbolAddress((void**)&oh,   g_oh);
    cudaGetSymbolAddress((void**)&ol,   g_ol);
    cudaGetSymbolAddress((void**)&hmh,  g_hmh);
    cudaGetSymbolAddress((void**)&hml,  g_hml);
    cudaGetSymbolAddress((void**)&x,    g_x);
    cudaGetSymbolAddress((void**)&feat, g_feat);
    cudaGetSymbolAddress((void**)&lb,   g_lb);
    cudaGetSymbolAddress((void**)&cls,  g_cls);

    static bool attr_done = false;
    if (!attr_done) {
        cudaFuncSetAttribute(mmagemm_k<EPI_STORE>,       cudaFuncAttributeMaxDynamicSharedMemorySize, SMTOT);
        cudaFuncSetAttribute(mmagemm_k<EPI_EMBED>,       cudaFuncAttributeMaxDynamicSharedMemorySize, SMTOT);
        cudaFuncSetAttribute(mmagemm_k<EPI_RESID>,       cudaFuncAttributeMaxDynamicSharedMemorySize, SMTOT);
        cudaFuncSetAttribute(mmagemm_k<EPI_GELU_PLANES>, cudaFuncAttributeMaxDynamicSharedMemorySize, SMTOT);
        cudaFuncSetAttribute(mmagemm_k<EPI_BIAS_RESID>,  cudaFuncAttributeMaxDynamicSharedMemorySize, SMTOT);
        attr_done = true;
    }

    patchln_k<<<NROWS_EMBED, 256>>>(img, spt_ln_g, spt_ln_b, ph, pl);
    cvtw_all_k<<<(int)((WTOT / 4 + 255) / 256), 256>>>(spt_w, in_proj_w, out_proj_w,
                                                       ff_w1, ff_w2, wh);
    cls_k<<<(BATCH * DMODEL + 255) / 256, 256>>>(cls_token, pos_emb, x);
    {
        dim3 grid(DMODEL / 128, NROWS_EMBED / 128);
        mmagemm_k<EPI_EMBED><<<grid, NTHREADS, SMTOT>>>(
            ph, pl, wh + WOFF_SPT,
            x, nullptr, spt_b, pos_emb, NROWS_EMBED, DMODEL, PD);
    }
    lb_k<<<(DMODEL + 255) / 256, 256>>>(lower_bounds, lb);

    for (int i = 0; i < DEPTH; i++) {
        rmsnorm_k<<<NT, 256>>>(x, xnh, xnl);
        {
            dim3 grid((3 * DMODEL) / 128, (NT + 127) / 128);
            mmagemm_k<EPI_STORE><<<grid, NTHREADS, SMTOT>>>(
                xnh, xnl,
                wh + WOFF_INP + (size_t)i * DMODEL * 3 * DMODEL,
                feat, nullptr, nullptr, nullptr, NT, 3 * DMODEL, DMODEL);
        }
        hgru_k<<<(TTOK * NHEAD + 255) / 256, 256>>>(feat, lb + (size_t)i * DMODEL, oh, ol);
        {
            dim3 grid(DMODEL / 128, (NT + 127) / 128);
            mmagemm_k<EPI_RESID><<<grid, NTHREADS, SMTOT>>>(
                oh, ol,
                wh + WOFF_OUTP + (size_t)i * DMODEL * DMODEL,
                x, nullptr, nullptr, nullptr, NT, DMODEL, DMODEL);
        }
        rmsnorm_k<<<NT, 256>>>(x, xnh, xnl);
        {
            dim3 grid(MLP / 128, (NT + 127) / 128);
            mmagemm_k<EPI_GELU_PLANES><<<grid, NTHREADS, SMTOT>>>(
                xnh, xnl,
                wh + WOFF_FF1 + (size_t)i * DMODEL * MLP,
                hmh, hml, ff_b1 + (size_t)i * MLP, nullptr, NT, MLP, DMODEL);
        }
        {
            dim3 grid(DMODEL / 128, (NT + 127) / 128);
            mmagemm_k<EPI_BIAS_RESID><<<grid, NTHREADS, SMTOT>>>(
                hmh, hml,
                wh + WOFF_FF2 + (size_t)i * MLP * DMODEL,
                x, nullptr, ff_b2 + (size_t)i * DMODEL, nullptr, NT, DMODEL, MLP);
        }
    }

    final_k<<<BATCH, 256>>>(x, head_ln_g, head_ln_b, cls);
    head_k<<<(BATCH * NCLS + 255) / 256, 256>>>(cls, head_w, head_b, (float*)d_out);
}

// round 9
// speedup vs baseline: 2.2419x; 1.7030x over previous
#include <cuda_runtime.h>
#include <cuda_fp16.h>
#include <math.h>
#include <stdint.h>

// ---------------------------------------------------------------------------
// Problem constants
// ---------------------------------------------------------------------------
#define BATCH   16
#define CIN     3
#define IMG     256
#define PSZ     16
#define NPATCH  256
#define C5      15
#define PD      3840
#define DMODEL  768
#define DEPTH   8
#define MLP     3072
#define NCLS    1000
#define TTOK    257
#define NT      (BATCH*TTOK)        // 4112
#define NROWS_EMBED (BATCH*NPATCH)  // 4096
#define NHEAD   384

// weight plane offsets (elements)
#define WOFF_SPT  0
#define WSZ_SPT   (PD*DMODEL)
#define WOFF_INP  (WOFF_SPT + WSZ_SPT)
#define WSZ_INP   (DEPTH*DMODEL*3*DMODEL)
#define WOFF_OUTP (WOFF_INP + WSZ_INP)
#define WSZ_OUTP  (DEPTH*DMODEL*DMODEL)
#define WOFF_FF1  (WOFF_OUTP + WSZ_OUTP)
#define WSZ_FF1   (DEPTH*DMODEL*MLP)
#define WOFF_FF2  (WOFF_FF1 + WSZ_FF1)
#define WSZ_FF2   (DEPTH*MLP*DMODEL)
#define WTOT      (WOFF_FF2 + WSZ_FF2)

// ---------------------------------------------------------------------------
// Scratch (device globals) — single fp16 plane everywhere
// ---------------------------------------------------------------------------
__device__ __half g_wh[WTOT];
__device__ __half g_ph[NROWS_EMBED * PD];
__device__ __half g_xnh[NT * DMODEL];
__device__ __half g_oh[NT * DMODEL];
__device__ __half g_hmh[NT * MLP];
__device__ float g_x[NT * DMODEL];
__device__ float g_feat[NT * 3 * DMODEL];
__device__ float g_lb[DEPTH * DMODEL];
__device__ float g_cls[BATCH * DMODEL];

// ---------------------------------------------------------------------------
// Helpers
// ---------------------------------------------------------------------------
__device__ __forceinline__ uint32_t smem_u32(const void* p) {
    uint32_t a;
    asm("{ .reg .u64 t; cvta.to.shared.u64 t, %1; cvt.u32.u64 %0, t; }"
        : "=r"(a) : "l"(p));
    return a;
}
__device__ __forceinline__ void ldsm4(uint32_t* r, uint32_t addr) {
    asm volatile("ldmatrix.sync.aligned.m8n8.x4.shared.b16 {%0,%1,%2,%3}, [%4];"
                 : "=r"(r[0]), "=r"(r[1]), "=r"(r[2]), "=r"(r[3]) : "r"(addr));
}
__device__ __forceinline__ void ldsm4t(uint32_t* r, uint32_t addr) {
    asm volatile("ldmatrix.sync.aligned.m8n8.x4.trans.shared.b16 {%0,%1,%2,%3}, [%4];"
                 : "=r"(r[0]), "=r"(r[1]), "=r"(r[2]), "=r"(r[3]) : "r"(addr));
}
__device__ __forceinline__ void mma16816(float* d, const uint32_t* a, const uint32_t* b) {
    asm volatile(
        "mma.sync.aligned.m16n8k16.row.col.f32.f16.f16.f32 "
        "{%0,%1,%2,%3}, {%4,%5,%6,%7}, {%8,%9}, {%0,%1,%2,%3};"
        : "+f"(d[0]), "+f"(d[1]), "+f"(d[2]), "+f"(d[3])
        : "r"(a[0]), "r"(a[1]), "r"(a[2]), "r"(a[3]), "r"(b[0]), "r"(b[1]));
}
__device__ __forceinline__ void cpasync16(uint32_t dst, const void* src, uint32_t n) {
    asm volatile("cp.async.cg.shared.global [%0], [%1], 16, %2;"
                 :: "r"(dst), "l"(src), "r"(n) : "memory");
}
__device__ __forceinline__ void cp_commit() {
    asm volatile("cp.async.commit_group;" ::: "memory");
}
template<int N>
__device__ __forceinline__ void cp_wait() {
    asm volatile("cp.async.wait_group %0;" :: "n"(N) : "memory");
}

__device__ __forceinline__ float gelu_exact(float x) {
    return 0.5f * x * (1.f + erff(x * 0.70710678118654752440f));
}

__device__ __forceinline__ float blockReduceSum(float v) {
    __shared__ float sh[32];
    __shared__ float res;
    int lane = threadIdx.x & 31;
    int wid  = threadIdx.x >> 5;
    #pragma unroll
    for (int o = 16; o > 0; o >>= 1) v += __shfl_down_sync(0xffffffffu, v, o);
    if (lane == 0) sh[wid] = v;
    __syncthreads();
    int nw = (blockDim.x + 31) >> 5;
    v = (threadIdx.x < nw) ? sh[threadIdx.x] : 0.f;
    if (wid == 0) {
        #pragma unroll
        for (int o = 16; o > 0; o >>= 1) v += __shfl_down_sync(0xffffffffu, v, o);
        if (lane == 0) res = v;
    }
    __syncthreads();
    return res;
}

__device__ __forceinline__ uint2 cvt4h(float4 v) {
    __half2 a = __floats2half2_rn(v.x, v.y);
    __half2 b = __floats2half2_rn(v.z, v.w);
    return make_uint2(*reinterpret_cast<uint32_t*>(&a), *reinterpret_cast<uint32_t*>(&b));
}

// ---------------------------------------------------------------------------
// Weight pre-conversion: all 5 weight tensors -> single fp16 plane, ONE launch
// ---------------------------------------------------------------------------
__global__ __launch_bounds__(256)
void cvtw_all_k(const float* __restrict__ spt, const float* __restrict__ inp,
                const float* __restrict__ outp, const float* __restrict__ f1,
                const float* __restrict__ f2, __half* __restrict__ h)
{
    size_t i = ((size_t)blockIdx.x * 256 + threadIdx.x) * 4;
    if (i >= WTOT) return;
    const float* src;
    size_t off;
    if (i < WOFF_INP)       { src = spt;  off = i - WOFF_SPT;  }
    else if (i < WOFF_OUTP) { src = inp;  off = i - WOFF_INP;  }
    else if (i < WOFF_FF1)  { src = outp; off = i - WOFF_OUTP; }
    else if (i < WOFF_FF2)  { src = f1;   off = i - WOFF_FF1;  }
    else                    { src = f2;   off = i - WOFF_FF2;  }
    float4 v = *reinterpret_cast<const float4*>(src + off);
    *reinterpret_cast<uint2*>(h + i) = cvt4h(v);
}

// ---------------------------------------------------------------------------
// cls row init
// ---------------------------------------------------------------------------
__global__ void cls_k(const float* __restrict__ cls_token,
                      const float* __restrict__ pos,
                      float* __restrict__ x)
{
    int i = blockIdx.x * blockDim.x + threadIdx.x;
    if (i >= BATCH * DMODEL) return;
    int b = i / DMODEL, d = i - b * DMODEL;
    x[(long)b * TTOK * DMODEL + d] = cls_token[d] + pos[d];
}

// ---------------------------------------------------------------------------
// HMMA GEMM, fp16 single-pass, cp.async 4-stage pipeline.
// CTA tile 128x128, K-chunk 32, 8 warps (2m x 4n), warp tile 64x32, 2 CTAs/SM.
// ---------------------------------------------------------------------------
#define EPI_STORE      0
#define EPI_EMBED      1
#define EPI_RESID      2
#define EPI_GELU_H     3
#define EPI_BIAS_RESID 4

#define NTHREADS 256
#define APITCH 80
#define BPITCH 272
#define OFF_A  0
#define OFF_B  10240
#define SBUF   18944        // 10240 + 32*272
#define STAGES 4
#define SMTOT  (STAGES*SBUF)   // 75776; x2 CTAs = 151552 < 228KB

__device__ __forceinline__ void stage_load(uint32_t sb,
                                           const __half* __restrict__ Ah,
                                           const __half* __restrict__ Bh,
                                           int M, int N, int lda,
                                           int rowBase, int colBase, int s, int tid)
{
    const int k0 = s << 5;
    // A: 128 rows x 64B; 512 16B chunks / 256 threads = 2 each
    {
        int row  = tid >> 1;
        int half = tid & 1;
        int gr   = rowBase + row;
        uint32_t nbytes = (gr < M) ? 16u : 0u;
        int grs = (gr < M) ? gr : (M - 1);
        size_t gbase = (size_t)grs * lda + k0 + half * 16;
        uint32_t sbase = (uint32_t)(row * APITCH + half * 32);
        cpasync16(sb + OFF_A + sbase,      Ah + gbase,     nbytes);
        cpasync16(sb + OFF_A + sbase + 16, Ah + gbase + 8, nbytes);
    }
    // B: 32 rows x 256B; 512 chunks / 256 threads = 2 each
    #pragma unroll
    for (int i = 0; i < 2; i++) {
        int idx = tid + i * 256;
        int row = idx >> 4;
        int seg = idx & 15;
        size_t goff = (size_t)(k0 + row) * N + colBase + seg * 8;
        uint32_t so = (uint32_t)(row * BPITCH + seg * 16);
        cpasync16(sb + OFF_B + so, Bh + goff, 16u);
    }
}

__device__ __forceinline__ void compute_chunk(uint32_t sbuf, int lane, int wm, int wn,
                                              float acc[4][4][4])
{
    #pragma unroll
    for (int k16 = 0; k16 < 32; k16 += 16) {
        const uint32_t arow = (uint32_t)(wm + (lane & 7) + (lane & 8));
        const uint32_t aoff = arow * APITCH + (uint32_t)(k16 + ((lane & 16) >> 1)) * 2;
        const uint32_t brow = (uint32_t)(k16 + (lane & 7) + ((lane & 16) >> 1));
        const uint32_t boff = brow * BPITCH + (uint32_t)(wn + (lane & 8)) * 2;

        uint32_t bH[2][4];
        #pragma unroll
        for (int nb2 = 0; nb2 < 2; nb2++)
            ldsm4t(bH[nb2], sbuf + OFF_B + boff + nb2 * 32);

        #pragma unroll
        for (int mb = 0; mb < 4; mb++) {
            uint32_t a[4];
            ldsm4(a, sbuf + OFF_A + aoff + mb * 16 * APITCH);
            #pragma unroll
            for (int nb = 0; nb < 4; nb++) {
                uint32_t bb[2] = { bH[nb >> 1][nb & 1], bH[nb >> 1][(nb & 1) + 2] };
                mma16816(acc[mb][nb], a, bb);
            }
        }
    }
}

template<int EPI>
__global__ __launch_bounds__(NTHREADS, 2)
void mmagemm_k(const __half* __restrict__ Ah, const __half* __restrict__ Bh,
               void* __restrict__ Cv,
               const float* __restrict__ bias, const float* __restrict__ extra,
               int M, int N, int K)
{
    extern __shared__ char smem[];
    const uint32_t sbase = smem_u32(smem);
    const int tid  = threadIdx.x;
    const int lane = tid & 31;
    const int wid  = tid >> 5;
    const int wm   = (wid >> 2) * 64;   // 2 m-warps
    const int wn   = (wid & 3) * 32;    // 4 n-warps
    const int rowBase = blockIdx.y * 128;
    const int colBase = blockIdx.x * 128;
    const int nc = K >> 5;

    float acc[4][4][4];
    #pragma unroll
    for (int a = 0; a < 4; a++)
        #pragma unroll
        for (int b = 0; b < 4; b++)
            #pragma unroll
            for (int c = 0; c < 4; c++) acc[a][b][c] = 0.f;

    #pragma unroll
    for (int s = 0; s < STAGES - 1; s++) {
        if (s < nc)
            stage_load(sbase + s * SBUF, Ah, Bh, M, N, K, rowBase, colBase, s, tid);
        cp_commit();
    }

    for (int c = 0; c < nc; c++) {
        cp_wait<STAGES - 2>();
        __syncthreads();
        int s = c + STAGES - 1;
        if (s < nc)
            stage_load(sbase + (s % STAGES) * SBUF, Ah, Bh, M, N, K,
                       rowBase, colBase, s, tid);
        cp_commit();
        compute_chunk(sbase + (c % STAGES) * SBUF, lane, wm, wn, acc);
    }

    // ---- epilogue ----
    const int mrow = rowBase + wm + (lane >> 2);
    const int mcol = colBase + wn + ((lane & 3) << 1);
    #pragma unroll
    for (int mi = 0; mi < 4; mi++) {
        #pragma unroll
        for (int hf = 0; hf < 2; hf++) {
            const int row = mrow + mi * 16 + hf * 8;
            if (row >= M) continue;
            #pragma unroll
            for (int ni = 0; ni < 4; ni++) {
                const int col = mcol + ni * 8;
                float v0 = acc[mi][ni][hf * 2];
                float v1 = acc[mi][ni][hf * 2 + 1];
                if (EPI == EPI_STORE) {
                    float* C = (float*)Cv;
                    *reinterpret_cast<float2*>(C + (size_t)row * N + col) =
                        make_float2(v0, v1);
                } else if (EPI == EPI_EMBED) {
                    float* C = (float*)Cv;
                    int b  = row >> 8;
                    int tl = row & 255;
                    float2 bb = *reinterpret_cast<const float2*>(bias + col);
                    float2 pp = *reinterpret_cast<const float2*>(extra + (size_t)(tl + 1) * N + col);
                    *reinterpret_cast<float2*>(C + ((size_t)b * TTOK + 1 + tl) * N + col) =
                        make_float2(v0 + bb.x + pp.x, v1 + bb.y + pp.y);
                } else if (EPI == EPI_RESID) {
                    float* C = (float*)Cv;
                    float2* o = reinterpret_cast<float2*>(C + (size_t)row * N + col);
                    float2 cc = *o;
                    *o = make_float2(cc.x + v0, cc.y + v1);
                } else if (EPI == EPI_GELU_H) {
                    __half* Hh = (__half*)Cv;
                    float2 bb = *reinterpret_cast<const float2*>(bias + col);
                    __half2 g = __floats2half2_rn(gelu_exact(v0 + bb.x),
                                                  gelu_exact(v1 + bb.y));
                    *reinterpret_cast<__half2*>(Hh + (size_t)row * N + col) = g;
                } else if (EPI == EPI_BIAS_RESID) {
                    float* C = (float*)Cv;
                    float2 bb = *reinterpret_cast<const float2*>(bias + col);
                    float2* o = reinterpret_cast<float2*>(C + (size_t)row * N + col);
                    float2 cc = *o;
                    *o = make_float2(cc.x + v0 + bb.x, cc.y + v1 + bb.y);
                }
            }
        }
    }
}

// ---------------------------------------------------------------------------
// Shifted-patch extraction + LayerNorm -> fp16 plane
// ---------------------------------------------------------------------------
__global__ __launch_bounds__(256)
void patchln_k(const float* __restrict__ img,
               const float* __restrict__ ln_g,
               const float* __restrict__ ln_b,
               __half* __restrict__ ph)
{
    const int blk = blockIdx.x;
    const int b   = blk >> 8;
    const int pt  = blk & 255;
    const int phh = pt >> 4;
    const int pw  = pt & 15;

    __shared__ float vals[PD];

    const int sh_tab[5] = {0, 0, 0, 1, -1};
    const int sw_tab[5] = {0, 1, -1, 0, 0};

    float s = 0.f, ss = 0.f;
    for (int f = threadIdx.x; f < PD; f += 256) {
        int py  = f / (PSZ * C5);
        int rem = f - py * (PSZ * C5);
        int px  = rem / C5;
        int c   = rem - px * C5;
        int g   = c / CIN;
        int ch  = c - g * CIN;
        int row = phh * PSZ + py - sh_tab[g];
        int col = pw * PSZ + px - sw_tab[g];
        float v = 0.f;
        if (row >= 0 && row < IMG && col >= 0 && col < IMG)
            v = img[(((long)b * CIN + ch) * IMG + row) * IMG + col];
        vals[f] = v;
        s  += v;
        ss += v * v;
    }
    float tsum  = blockReduceSum(s);
    float tsum2 = blockReduceSum(ss);
    float mean  = tsum * (1.f / PD);
    float var   = tsum2 * (1.f / PD) - mean * mean;
    float rstd  = rsqrtf(var + 1e-5f);
    __syncthreads();
    size_t rowoff = (size_t)blk * PD;
    for (int f = threadIdx.x; f < PD; f += 256) {
        float y = (vals[f] - mean) * rstd * ln_g[f] + ln_b[f];
        ph[rowoff + f] = __float2half_rn(y);
    }
}

// ---------------------------------------------------------------------------
__global__ void lb_k(const float* __restrict__ lbin, float* __restrict__ lbout)
{
    int d = blockIdx.x * blockDim.x + threadIdx.x;
    if (d >= DMODEL) return;
    float v[DEPTH];
    float m = -1e30f;
    #pragma unroll
    for (int i = 0; i < DEPTH; i++) { v[i] = lbin[i * DMODEL + d]; m = fmaxf(m, v[i]); }
    float s = 0.f;
    #pragma unroll
    for (int i = 0; i < DEPTH; i++) { v[i] = expf(v[i] - m); s += v[i]; }
    float inv = 1.f / s;
    float c = 0.f;
    float c0 = v[0] * inv;
    #pragma unroll
    for (int i = 0; i < DEPTH; i++) { c += v[i] * inv; lbout[i * DMODEL + d] = c - c0; }
}

// RMSNorm -> fp16 plane
__global__ __launch_bounds__(256)
void rmsnorm_k(const float* __restrict__ x, __half* __restrict__ yh)
{
    const long row = blockIdx.x;
    const float* xr = x + row * DMODEL;
    float s = 0.f;
    for (int i = threadIdx.x; i < DMODEL; i += 256) { float v = xr[i]; s += v * v; }
    float tot = blockReduceSum(s);
    float r = rsqrtf(tot * (1.f / DMODEL) + 1e-6f);
    size_t off = (size_t)row * DMODEL;
    for (int i = threadIdx.x; i < DMODEL; i += 256)
        yh[off + i] = __float2half_rn(xr[i] * r);
}

// hGRU2 scan -> fp16 plane
__global__ __launch_bounds__(256)
void hgru_k(const float* __restrict__ feat, const float* __restrict__ lb,
            __half* __restrict__ oh)
{
    int e = blockIdx.x * blockDim.x + threadIdx.x;
    if (e >= TTOK * NHEAD) return;
    int t = e / NHEAD;
    int h = e - t * NHEAD;

    float lb0 = lb[2 * h];
    float lb1 = lb[2 * h + 1];
    float S00 = 0.f, S01 = 0.f, S10 = 0.f, S11 = 0.f;

    #pragma unroll 1
    for (int n = 0; n < BATCH; n++) {
        const float* r = feat + (long)(n * TTOK + t) * (3 * DMODEL);
        float2 vv = *(const float2*)(r + 2 * h);
        float2 qq = *(const float2*)(r + DMODEL + 2 * h);
        float2 ff = *(const float2*)(r + 2 * DMODEL + 2 * h);
        float v0 = gelu_exact(vv.x), v1 = gelu_exact(vv.y);
        float q0 = gelu_exact(qq.x), q1 = gelu_exact(qq.y);
        float s0 = 1.f / (1.f + expf(-ff.x));
        float s1 = 1.f / (1.f + expf(-ff.y));
        float lam0 = lb0 + (1.f - lb0) * s0;
        float lam1 = lb1 + (1.f - lb1) * s1;
        float k0 = 1.f - lam0, k1 = 1.f - lam1;
        S00 = lam0 * S00 + k0 * v0;  S01 = lam0 * S01 + k0 * v1;
        S10 = lam1 * S10 + k1 * v0;  S11 = lam1 * S11 + k1 * v1;
        float o0 = q0 * S00 + q1 * S10;
        float o1 = q0 * S01 + q1 * S11;
        __half2 p = __floats2half2_rn(o0, o1);
        *reinterpret_cast<__half2*>(oh + (size_t)(n * TTOK + t) * DMODEL + 2 * h) = p;
    }
}

__global__ __launch_bounds__(256)
void final_k(const float* __restrict__ x,
             const float* __restrict__ g, const float* __restrict__ bvec,
             float* __restrict__ cls)
{
    int b = blockIdx.x;
    const float* xr = x + (long)b * TTOK * DMODEL;
    __shared__ float y[DMODEL];
    float s = 0.f, ss = 0.f;
    for (int i = threadIdx.x; i < DMODEL; i += 256) {
        float v = xr[i];
        y[i] = v;
        s  += v;
        ss += v * v;
    }
    float tsum  = blockReduceSum(s);
    float tsum2 = blockReduceSum(ss);
    float rstd1 = rsqrtf(tsum2 * (1.f / DMODEL) + 1e-6f);
    float mean  = rstd1 * tsum * (1.f / DMODEL);
    float ez2   = rstd1 * rstd1 * tsum2 * (1.f / DMODEL);
    float var   = ez2 - mean * mean;
    float rstd2 = rsqrtf(var + 1e-5f);
    __syncthreads();
    for (int i = threadIdx.x; i < DMODEL; i += 256) {
        float z = y[i] * rstd1;
        cls[(long)b * DMODEL + i] = (z - mean) * rstd2 * g[i] + bvec[i];
    }
}

__global__ __launch_bounds__(256)
void head_k(const float* __restrict__ cls, const float* __restrict__ w,
            const float* __restrict__ bias, float* __restrict__ out)
{
    int idx = blockIdx.x * blockDim.x + threadIdx.x;
    if (idx >= BATCH * NCLS) return;
    int b = idx / NCLS, c = idx - b * NCLS;
    const float* xr = cls + (long)b * DMODEL;
    float s = bias[c];
    #pragma unroll 4
    for (int k = 0; k < DMODEL; k++)
        s = fmaf(xr[k], w[(long)k * NCLS + c], s);
    out[idx] = s;
}

// ---------------------------------------------------------------------------
// Launch
// ---------------------------------------------------------------------------
extern "C" void kernel_launch(void* const* d_in, const int* in_sizes, int n_in,
                              void* d_out, int out_size)
{
    const float* img          = (const float*)d_in[0];
    const float* spt_ln_g     = (const float*)d_in[1];
    const float* spt_ln_b     = (const float*)d_in[2];
    const float* spt_w        = (const float*)d_in[3];
    const float* spt_b        = (const float*)d_in[4];
    const float* pos_emb      = (const float*)d_in[5];
    const float* cls_token    = (const float*)d_in[6];
    const float* lower_bounds = (const float*)d_in[7];
    const float* in_proj_w    = (const float*)d_in[8];
    const float* out_proj_w   = (const float*)d_in[9];
    const float* ff_w1        = (const float*)d_in[10];
    const float* ff_b1        = (const float*)d_in[11];
    const float* ff_w2        = (const float*)d_in[12];
    const float* ff_b2        = (const float*)d_in[13];
    const float* head_ln_g    = (const float*)d_in[14];
    const float* head_ln_b    = (const float*)d_in[15];
    const float* head_w       = (const float*)d_in[16];
    const float* head_b       = (const float*)d_in[17];

    __half *wh, *ph, *xnh, *oh, *hmh;
    float *x, *feat, *lb, *cls;
    cudaGetSymbolAddress((void**)&wh,   g_wh);
    cudaGetSymbolAddress((void**)&ph,   g_ph);
    cudaGetSymbolAddress((void**)&xnh,  g_xnh);
    cudaGetSymbolAddress((void**)&oh,   g_oh);
    cudaGetSymbolAddress((void**)&hmh,  g_hmh);
    cudaGetSymbolAddress((void**)&x,    g_x);
    cudaGetSymbolAddress((void**)&feat, g_feat);
    cudaGetSymbolAddress((void**)&lb,   g_lb);
    cudaGetSymbolAddress((void**)&cls,  g_cls);

    static bool attr_done = false;
    if (!attr_done) {
        cudaFuncSetAttribute(mmagemm_k<EPI_STORE>,      cudaFuncAttributeMaxDynamicSharedMemorySize, SMTOT);
        cudaFuncSetAttribute(mmagemm_k<EPI_EMBED>,      cudaFuncAttributeMaxDynamicSharedMemorySize, SMTOT);
        cudaFuncSetAttribute(mmagemm_k<EPI_RESID>,      cudaFuncAttributeMaxDynamicSharedMemorySize, SMTOT);
        cudaFuncSetAttribute(mmagemm_k<EPI_GELU_H>,     cudaFuncAttributeMaxDynamicSharedMemorySize, SMTOT);
        cudaFuncSetAttribute(mmagemm_k<EPI_BIAS_RESID>, cudaFuncAttributeMaxDynamicSharedMemorySize, SMTOT);
        attr_done = true;
    }

    patchln_k<<<NROWS_EMBED, 256>>>(img, spt_ln_g, spt_ln_b, ph);
    cvtw_all_k<<<(int)((WTOT / 4 + 255) / 256), 256>>>(spt_w, in_proj_w, out_proj_w,
                                                       ff_w1, ff_w2, wh);
    cls_k<<<(BATCH * DMODEL + 255) / 256, 256>>>(cls_token, pos_emb, x);
    {
        dim3 grid(DMODEL / 128, NROWS_EMBED / 128);
        mmagemm_k<EPI_EMBED><<<grid, NTHREADS, SMTOT>>>(
            ph, wh + WOFF_SPT, x, spt_b, pos_emb, NROWS_EMBED, DMODEL, PD);
    }
    lb_k<<<(DMODEL + 255) / 256, 256>>>(lower_bounds, lb);

    for (int i = 0; i < DEPTH; i++) {
        rmsnorm_k<<<NT, 256>>>(x, xnh);
        {
            dim3 grid((3 * DMODEL) / 128, (NT + 127) / 128);
            mmagemm_k<EPI_STORE><<<grid, NTHREADS, SMTOT>>>(
                xnh, wh + WOFF_INP + (size_t)i * DMODEL * 3 * DMODEL,
                feat, nullptr, nullptr, NT, 3 * DMODEL, DMODEL);
        }
        hgru_k<<<(TTOK * NHEAD + 255) / 256, 256>>>(feat, lb + (size_t)i * DMODEL, oh);
        {
            dim3 grid(DMODEL / 128, (NT + 127) / 128);
            mmagemm_k<EPI_RESID><<<grid, NTHREADS, SMTOT>>>(
                oh, wh + WOFF_OUTP + (size_t)i * DMODEL * DMODEL,
                x, nullptr, nullptr, NT, DMODEL, DMODEL);
        }
        rmsnorm_k<<<NT, 256>>>(x, xnh);
        {
            dim3 grid(MLP / 128, (NT + 127) / 128);
            mmagemm_k<EPI_GELU_H><<<grid, NTHREADS, SMTOT>>>(
                xnh, wh + WOFF_FF1 + (size_t)i * DMODEL * MLP,
                hmh, ff_b1 + (size_t)i * MLP, nullptr, NT, MLP, DMODEL);
        }
        {
            dim3 grid(DMODEL / 128, (NT + 127) / 128);
            mmagemm_k<EPI_BIAS_RESID><<<grid, NTHREADS, SMTOT>>>(
                hmh, wh + WOFF_FF2 + (size_t)i * MLP * DMODEL,
                x, ff_b2 + (size_t)i * DMODEL, nullptr, NT, DMODEL, MLP);
        }
    }

    final_k<<<BATCH, 256>>>(x, head_ln_g, head_ln_b, cls);
    head_k<<<(BATCH * NCLS + 255) / 256, 256>>>(cls, head_w, head_b, (float*)d_out);
}